// round 9
// baseline (speedup 1.0000x reference)
#include <cuda_runtime.h>
#include <cuda_bf16.h>
#include <cstdint>

#define BB 2
#define SS 2048
#define DD 512
#define HH 8
#define LR 7
#define MTOT (BB*SS)        // 4096
#define K3 (3*DD)           // 1536

// scratch
__device__ float g_q[MTOT * DD];
__device__ float g_k[MTOT * DD];
__device__ float g_w[MTOT * 128];           // [b*S+i][jj*8+h] normalized band weights
__device__ __nv_bfloat16 g_a3[MTOT * K3];   // [hi | lo | hi] along K
__device__ __nv_bfloat16 g_b3q[DD * K3];    // [hi | hi | lo] along K, rows = n
__device__ __nv_bfloat16 g_b3k[DD * K3];

#define SWZ128(off) ((off) ^ (((off) >> 3) & 0x70))

__device__ __forceinline__ uint32_t smem_u32(const void* p) {
    uint32_t a;
    asm("{ .reg .u64 t; cvta.to.shared.u64 t, %1; cvt.u32.u64 %0, t; }" : "=r"(a) : "l"(p));
    return a;
}
__device__ __forceinline__ void cp16(uint32_t s, const void* g) {
    asm volatile("cp.async.cg.shared.global [%0], [%1], 16;" :: "r"(s), "l"(g));
}
#define CP_COMMIT() asm volatile("cp.async.commit_group;" ::: "memory")

__device__ __forceinline__ void ldm_x4(uint32_t& r0, uint32_t& r1, uint32_t& r2, uint32_t& r3, uint32_t a) {
    asm volatile("ldmatrix.sync.aligned.m8n8.x4.shared.b16 {%0,%1,%2,%3}, [%4];"
                 : "=r"(r0), "=r"(r1), "=r"(r2), "=r"(r3) : "r"(a));
}
__device__ __forceinline__ void ldm_x2(uint32_t& r0, uint32_t& r1, uint32_t a) {
    asm volatile("ldmatrix.sync.aligned.m8n8.x2.shared.b16 {%0,%1}, [%2];"
                 : "=r"(r0), "=r"(r1) : "r"(a));
}
__device__ __forceinline__ void mma16816(float* d, const uint32_t* a, const uint32_t* b) {
    asm volatile("mma.sync.aligned.m16n8k16.row.col.f32.bf16.bf16.f32 "
                 "{%0,%1,%2,%3}, {%4,%5,%6,%7}, {%8,%9}, {%0,%1,%2,%3};"
                 : "+f"(d[0]), "+f"(d[1]), "+f"(d[2]), "+f"(d[3])
                 : "r"(a[0]), "r"(a[1]), "r"(a[2]), "r"(a[3]), "r"(b[0]), "r"(b[1]));
}

// ---------------------------------------------------------------------------
// split hidden_states into bf16 hi/lo, tripled K layout [hi|lo|hi]
// ---------------------------------------------------------------------------
__global__ void split_hs(const float* __restrict__ hs) {
    int idx = blockIdx.x * 256 + threadIdx.x;
    int m = idx >> 7;
    int c = idx & 127;
    float4 v = ((const float4*)hs)[idx];
    __nv_bfloat16 hx = __float2bfloat16(v.x), hy = __float2bfloat16(v.y);
    __nv_bfloat16 hz = __float2bfloat16(v.z), hw = __float2bfloat16(v.w);
    __nv_bfloat16 lx = __float2bfloat16(v.x - __bfloat162float(hx));
    __nv_bfloat16 ly = __float2bfloat16(v.y - __bfloat162float(hy));
    __nv_bfloat16 lz = __float2bfloat16(v.z - __bfloat162float(hz));
    __nv_bfloat16 lw = __float2bfloat16(v.w - __bfloat162float(hw));
    __nv_bfloat162 H0; H0.x = hx; H0.y = hy;
    __nv_bfloat162 H1; H1.x = hz; H1.y = hw;
    __nv_bfloat162 L0; L0.x = lx; L0.y = ly;
    __nv_bfloat162 L1; L1.x = lz; L1.y = lw;
    __nv_bfloat16* p = g_a3 + (size_t)m * K3 + 4 * c;
    *(__nv_bfloat162*)(p)          = H0; *(__nv_bfloat162*)(p + 2)          = H1;
    *(__nv_bfloat162*)(p + DD)     = L0; *(__nv_bfloat162*)(p + DD + 2)     = L1;
    *(__nv_bfloat162*)(p + 2*DD)   = H0; *(__nv_bfloat162*)(p + 2*DD + 2)   = H1;
}

// ---------------------------------------------------------------------------
// split + transpose W (stored [k, n]) into B3 [n, 3K] = [hi|hi|lo]
// ---------------------------------------------------------------------------
__global__ void split_w(const float* __restrict__ Wq, const float* __restrict__ Wk) {
    __shared__ float t[32][33];
    const float* W = blockIdx.z ? Wk : Wq;
    __nv_bfloat16* B3 = blockIdx.z ? g_b3k : g_b3q;
    int n0 = blockIdx.x * 32, k0 = blockIdx.y * 32;
    int tx = threadIdx.x, ty = threadIdx.y;
#pragma unroll
    for (int r = 0; r < 4; r++)
        t[ty + r * 8][tx] = W[(size_t)(k0 + ty + r * 8) * DD + n0 + tx];
    __syncthreads();
#pragma unroll
    for (int r = 0; r < 4; r++) {
        int n = n0 + ty + r * 8, k = k0 + tx;
        float v = t[tx][ty + r * 8];
        __nv_bfloat16 h = __float2bfloat16(v);
        __nv_bfloat16 l = __float2bfloat16(v - __bfloat162float(h));
        B3[(size_t)n * K3 + k]        = h;
        B3[(size_t)n * K3 + DD + k]   = h;
        B3[(size_t)n * K3 + 2*DD + k] = l;
    }
}

// ---------------------------------------------------------------------------
// mma.sync bf16 GEMM: C[4096,512] = A3[4096,1536] * B3[512,1536]^T, f32 acc
// ---------------------------------------------------------------------------
#define MT 128
#define NT 128
#define KT 64
#define NK 24
#define STG 32768u
#define NSTG 3
#define GEMM_SMEM (NSTG * STG)

__device__ __forceinline__ void load_tile(int tile, int stg,
                                          const char* Ab, const char* Bb,
                                          uint32_t sb, int tid) {
    size_t koff = (size_t)tile * (KT * 2);
    uint32_t sA = sb + (uint32_t)stg * STG;
    uint32_t sB = sA + 16384u;
#pragma unroll
    for (int c = 0; c < 4; c++) {
        int q = tid + c * 256;
        int r = q >> 3, col = (q & 7) * 16;
        cp16(sA + SWZ128(r * 128 + col), Ab + (size_t)r * (K3 * 2) + koff + col);
    }
#pragma unroll
    for (int c = 0; c < 4; c++) {
        int q = tid + c * 256;
        int r = q >> 3, col = (q & 7) * 16;
        cp16(sB + SWZ128(r * 128 + col), Bb + (size_t)r * (K3 * 2) + koff + col);
    }
}

__global__ __launch_bounds__(256, 2)
void gemm3() {
    extern __shared__ char smem[];
    uint32_t sb = smem_u32(smem);
    const int tid = threadIdx.x, wid = tid >> 5, lane = tid & 31;
    const int m0 = blockIdx.x * MT;
    const int n0 = blockIdx.y * NT;
    const __nv_bfloat16* B3 = blockIdx.z ? g_b3k : g_b3q;
    float* C = blockIdx.z ? g_k : g_q;

    const char* Ab = (const char*)g_a3 + (size_t)m0 * (K3 * 2);
    const char* Bb = (const char*)B3 + (size_t)n0 * (K3 * 2);

    const int wm = wid & 1;
    const int wn = wid >> 1;

    float acc[4][4][4];
#pragma unroll
    for (int i = 0; i < 4; i++)
#pragma unroll
        for (int j = 0; j < 4; j++)
#pragma unroll
            for (int r = 0; r < 4; r++) acc[i][j][r] = 0.f;

    load_tile(0, 0, Ab, Bb, sb, tid); CP_COMMIT();
    load_tile(1, 1, Ab, Bb, sb, tid); CP_COMMIT();

    const int a_row = wm * 64 + (lane & 15);
    const int a_cg  = (lane >> 4) * 16;
    const int b_row = wn * 32 + (lane & 7);
    const int b_cg  = ((lane >> 3) & 1) * 16;

    for (int t = 0; t < NK; t++) {
        asm volatile("cp.async.wait_group 1;" ::: "memory");
        __syncthreads();

        if (t + 2 < NK)
            load_tile(t + 2, (t + 2) % NSTG, Ab, Bb, sb, tid);
        CP_COMMIT();

        uint32_t sA = sb + (uint32_t)(t % NSTG) * STG;
        uint32_t sB = sA + 16384u;
#pragma unroll
        for (int ks = 0; ks < 4; ks++) {
            uint32_t af[4][4], bf[4][2];
#pragma unroll
            for (int mi = 0; mi < 4; mi++)
                ldm_x4(af[mi][0], af[mi][1], af[mi][2], af[mi][3],
                       sA + SWZ128((a_row + mi * 16) * 128 + ks * 32 + a_cg));
#pragma unroll
            for (int ni = 0; ni < 4; ni++)
                ldm_x2(bf[ni][0], bf[ni][1],
                       sB + SWZ128((b_row + ni * 8) * 128 + ks * 32 + b_cg));
#pragma unroll
            for (int mi = 0; mi < 4; mi++)
#pragma unroll
                for (int ni = 0; ni < 4; ni++)
                    mma16816(acc[mi][ni], af[mi], bf[ni]);
        }
    }

    const int er = lane >> 2;
    const int ec = (lane & 3) * 2;
#pragma unroll
    for (int mi = 0; mi < 4; mi++) {
        int r0 = m0 + wm * 64 + mi * 16 + er;
#pragma unroll
        for (int ni = 0; ni < 4; ni++) {
            int cc = n0 + wn * 32 + ni * 8 + ec;
            *(float2*)(C + (size_t)r0 * DD + cc) = make_float2(acc[mi][ni][0], acc[mi][ni][1]);
            *(float2*)(C + (size_t)(r0 + 8) * DD + cc) = make_float2(acc[mi][ni][2], acc[mi][ni][3]);
        }
    }
}

// ---------------------------------------------------------------------------
// wts v5: block = 16 consecutive i (512 thr), 30 k rows staged in smem.
// warp = one i; lane owns 16 floats of head (lane>>2).
// Writes scalar weights, TRANSPOSED layout [i][jj*8+h].
// ---------------------------------------------------------------------------
#define WTS_SMEM (30 * DD * 4)    // 61440

__global__ __launch_bounds__(512)
void wts() {
    extern __shared__ float sk[];           // [30][512], swizzled
    float4* sk4 = (float4*)sk;

    const int b = blockIdx.y;
    const int i0 = blockIdx.x * 16;
    const int tid = threadIdx.x;

    for (int idx = tid; idx < 30 * 128; idx += 512) {
        int r = idx >> 7, p = idx & 127;
        int j = i0 - LR + r;
        j = j < 0 ? 0 : (j >= SS ? SS - 1 : j);
        int ps = p ^ (((p >> 4) & 1) << 2);
        sk4[r * 128 + ps] = ((const float4*)(g_k + ((size_t)b * SS + j) * DD))[p];
    }
    __syncthreads();

    const int wid = tid >> 5, lane = tid & 31;
    const int i = i0 + wid;
    const int h = lane >> 2, g = lane & 3;
    const int flip = (h & 1) << 2;

    const float4* q4 = (const float4*)(g_q + ((size_t)b * SS + i) * DD);
    float4 ql[4];
#pragma unroll
    for (int t = 0; t < 4; t++) ql[t] = q4[16 * h + g + 4 * t];

    float sc[15];
#pragma unroll
    for (int jj = 0; jj < 15; jj++) {
        int j = i - LR + jj;
        bool valid = (j >= 0) && (j < SS);
        const float4* kr = sk4 + (wid + jj) * 128;
        float p = 0.f;
#pragma unroll
        for (int t = 0; t < 4; t++) {
            float4 kv = kr[(16 * h + g + 4 * t) ^ flip];
            p += ql[t].x * kv.x + ql[t].y * kv.y + ql[t].z * kv.z + ql[t].w * kv.w;
        }
        p += __shfl_xor_sync(0xffffffffu, p, 1);
        p += __shfl_xor_sync(0xffffffffu, p, 2);
        sc[jj] = valid ? p * 0.125f : -1e30f;
    }

    float m = -1e30f;
#pragma unroll
    for (int jj = 0; jj < 15; jj++) m = fmaxf(m, sc[jj]);
    float s = 0.f;
#pragma unroll
    for (int jj = 0; jj < 15; jj++) { sc[jj] = __expf(sc[jj] - m); s += sc[jj]; }
    float inv = 1.f / s;

    float* wp = g_w + (((size_t)b * SS + i) << 7);
#pragma unroll
    for (int jj = g; jj < 15; jj += 4)
        wp[jj * 8 + h] = sc[jj] * inv;
}

// ---------------------------------------------------------------------------
// ctx v5: out[b,h,i,:] = sum_jj w * hs[b, i-7+jj, :], scalar FFMA
// block = 32 i x 256 d; grid (64, 2, 2); 62 KB smem -> 3 CTAs/SM
// weights [il][jj*8+h] float in smem: per jj, 2x float4 broadcast loads
// ---------------------------------------------------------------------------
#define CTX_SMEM (46 * 256 * 4 + 32 * 128 * 4)   // 47104 + 16384 = 63488

__global__ __launch_bounds__(256, 3)
void ctx(const float* __restrict__ hs, float* __restrict__ out) {
    extern __shared__ char smemraw[];
    float* sh = (float*)smemraw;                          // [46][256]
    float* sw = (float*)(smemraw + 46 * 256 * 4);         // [32][128] (jj*8+h)

    const int ic = blockIdx.x, dc = blockIdx.y, b = blockIdx.z;
    const int i0 = ic * 32, d0 = dc * 256;
    const int tid = threadIdx.x;

    for (int idx = tid; idx < 46 * 64; idx += 256) {
        int r = idx >> 6, c = idx & 63;
        int j = i0 - LR + r;
        j = j < 0 ? 0 : (j >= SS ? SS - 1 : j);
        ((float4*)sh)[idx] = ((const float4*)(hs + ((size_t)b * SS + j) * DD + d0))[c];
    }
    {
        const float4* gw4 = (const float4*)(g_w + (((size_t)b * SS + i0) << 7));
        for (int idx = tid; idx < 1024; idx += 256)
            ((float4*)sw)[idx] = gw4[idx];
    }
    __syncthreads();

    const int wid = tid >> 5, lane = tid & 31;
    const float4* sh4 = (const float4*)sh;     // row stride 64 float4

#pragma unroll
    for (int ii = 0; ii < 4; ii++) {
        const int il = ii * 8 + wid;
        const int ig = i0 + il;
        const float* wp = &sw[il * 128];
#pragma unroll
        for (int cp = 0; cp < 2; cp++) {
            const int c4 = lane + 32 * cp;                 // float4 col 0..63
            float4 acc[HH];
#pragma unroll
            for (int h = 0; h < HH; h++) { acc[h].x = acc[h].y = acc[h].z = acc[h].w = 0.f; }
#pragma unroll
            for (int jj = 0; jj < 15; jj++) {
                float4 v = sh4[(il + jj) * 64 + c4];
                float4 wa = *(const float4*)(wp + jj * 8);       // heads 0..3
                float4 wb = *(const float4*)(wp + jj * 8 + 4);   // heads 4..7
                acc[0].x += wa.x * v.x; acc[0].y += wa.x * v.y; acc[0].z += wa.x * v.z; acc[0].w += wa.x * v.w;
                acc[1].x += wa.y * v.x; acc[1].y += wa.y * v.y; acc[1].z += wa.y * v.z; acc[1].w += wa.y * v.w;
                acc[2].x += wa.z * v.x; acc[2].y += wa.z * v.y; acc[2].z += wa.z * v.z; acc[2].w += wa.z * v.w;
                acc[3].x += wa.w * v.x; acc[3].y += wa.w * v.y; acc[3].z += wa.w * v.z; acc[3].w += wa.w * v.w;
                acc[4].x += wb.x * v.x; acc[4].y += wb.x * v.y; acc[4].z += wb.x * v.z; acc[4].w += wb.x * v.w;
                acc[5].x += wb.y * v.x; acc[5].y += wb.y * v.y; acc[5].z += wb.y * v.z; acc[5].w += wb.y * v.w;
                acc[6].x += wb.z * v.x; acc[6].y += wb.z * v.y; acc[6].z += wb.z * v.z; acc[6].w += wb.z * v.w;
                acc[7].x += wb.w * v.x; acc[7].y += wb.w * v.y; acc[7].z += wb.w * v.z; acc[7].w += wb.w * v.w;
            }
#pragma unroll
            for (int h = 0; h < HH; h++)
                *(float4*)(out + (((size_t)b * HH + h) * SS + ig) * DD + d0 + c4 * 4) = acc[h];
        }
    }
}

// ---------------------------------------------------------------------------
extern "C" void kernel_launch(void* const* d_in, const int* in_sizes, int n_in,
                              void* d_out, int out_size) {
    const float* hs = (const float*)d_in[0];
    const float* Wq = (const float*)d_in[1];
    const float* Wk = (const float*)d_in[2];
    float* out = (float*)d_out;

    cudaFuncSetAttribute(gemm3, cudaFuncAttributeMaxDynamicSharedMemorySize, GEMM_SMEM);
    cudaFuncSetAttribute(ctx, cudaFuncAttributeMaxDynamicSharedMemorySize, CTX_SMEM);
    cudaFuncSetAttribute(wts, cudaFuncAttributeMaxDynamicSharedMemorySize, WTS_SMEM);

    split_hs<<<2048, 256>>>(hs);
    split_w<<<dim3(16, 16, 2), dim3(32, 8)>>>(Wq, Wk);
    gemm3<<<dim3(32, 4, 2), 256, GEMM_SMEM>>>();
    wts<<<dim3(SS / 16, BB), 512, WTS_SMEM>>>();
    ctx<<<dim3(64, 2, 2), 256, CTX_SMEM>>>(hs, out);
}

// round 10
// speedup vs baseline: 1.3389x; 1.3389x over previous
#include <cuda_runtime.h>
#include <cuda_bf16.h>
#include <cstdint>

#define BB 2
#define SS 2048
#define DD 512
#define HH 8
#define LR 7
#define MTOT (BB*SS)        // 4096
#define K3 (3*DD)           // 1536

// scratch
__device__ float g_q[MTOT * DD];
__device__ float g_k[MTOT * DD];
__device__ float g_w[MTOT * 128];           // [b*S+i][jj*8+h] normalized band weights
__device__ __nv_bfloat16 g_a3[MTOT * K3];   // [hi | lo | hi] along K
__device__ __nv_bfloat16 g_b3q[DD * K3];    // [hi | hi | lo] along K, rows = n
__device__ __nv_bfloat16 g_b3k[DD * K3];

#define SWZ128(off) ((off) ^ (((off) >> 3) & 0x70))

__device__ __forceinline__ uint32_t smem_u32(const void* p) {
    uint32_t a;
    asm("{ .reg .u64 t; cvta.to.shared.u64 t, %1; cvt.u32.u64 %0, t; }" : "=r"(a) : "l"(p));
    return a;
}
__device__ __forceinline__ void cp16(uint32_t s, const void* g) {
    asm volatile("cp.async.cg.shared.global [%0], [%1], 16;" :: "r"(s), "l"(g));
}
#define CP_COMMIT() asm volatile("cp.async.commit_group;" ::: "memory")

__device__ __forceinline__ void ldm_x4(uint32_t& r0, uint32_t& r1, uint32_t& r2, uint32_t& r3, uint32_t a) {
    asm volatile("ldmatrix.sync.aligned.m8n8.x4.shared.b16 {%0,%1,%2,%3}, [%4];"
                 : "=r"(r0), "=r"(r1), "=r"(r2), "=r"(r3) : "r"(a));
}
__device__ __forceinline__ void ldm_x2(uint32_t& r0, uint32_t& r1, uint32_t a) {
    asm volatile("ldmatrix.sync.aligned.m8n8.x2.shared.b16 {%0,%1}, [%2];"
                 : "=r"(r0), "=r"(r1) : "r"(a));
}
__device__ __forceinline__ void mma16816(float* d, const uint32_t* a, const uint32_t* b) {
    asm volatile("mma.sync.aligned.m16n8k16.row.col.f32.bf16.bf16.f32 "
                 "{%0,%1,%2,%3}, {%4,%5,%6,%7}, {%8,%9}, {%0,%1,%2,%3};"
                 : "+f"(d[0]), "+f"(d[1]), "+f"(d[2]), "+f"(d[3])
                 : "r"(a[0]), "r"(a[1]), "r"(a[2]), "r"(a[3]), "r"(b[0]), "r"(b[1]));
}

// ---------------------------------------------------------------------------
// split hidden_states into bf16 hi/lo, tripled K layout [hi|lo|hi]
// ---------------------------------------------------------------------------
__global__ void split_hs(const float* __restrict__ hs) {
    int idx = blockIdx.x * 256 + threadIdx.x;
    int m = idx >> 7;
    int c = idx & 127;
    float4 v = ((const float4*)hs)[idx];
    __nv_bfloat16 hx = __float2bfloat16(v.x), hy = __float2bfloat16(v.y);
    __nv_bfloat16 hz = __float2bfloat16(v.z), hw = __float2bfloat16(v.w);
    __nv_bfloat16 lx = __float2bfloat16(v.x - __bfloat162float(hx));
    __nv_bfloat16 ly = __float2bfloat16(v.y - __bfloat162float(hy));
    __nv_bfloat16 lz = __float2bfloat16(v.z - __bfloat162float(hz));
    __nv_bfloat16 lw = __float2bfloat16(v.w - __bfloat162float(hw));
    __nv_bfloat162 H0; H0.x = hx; H0.y = hy;
    __nv_bfloat162 H1; H1.x = hz; H1.y = hw;
    __nv_bfloat162 L0; L0.x = lx; L0.y = ly;
    __nv_bfloat162 L1; L1.x = lz; L1.y = lw;
    __nv_bfloat16* p = g_a3 + (size_t)m * K3 + 4 * c;
    *(__nv_bfloat162*)(p)          = H0; *(__nv_bfloat162*)(p + 2)          = H1;
    *(__nv_bfloat162*)(p + DD)     = L0; *(__nv_bfloat162*)(p + DD + 2)     = L1;
    *(__nv_bfloat162*)(p + 2*DD)   = H0; *(__nv_bfloat162*)(p + 2*DD + 2)   = H1;
}

// ---------------------------------------------------------------------------
// split + transpose W (stored [k, n]) into B3 [n, 3K] = [hi|hi|lo]
// ---------------------------------------------------------------------------
__global__ void split_w(const float* __restrict__ Wq, const float* __restrict__ Wk) {
    __shared__ float t[32][33];
    const float* W = blockIdx.z ? Wk : Wq;
    __nv_bfloat16* B3 = blockIdx.z ? g_b3k : g_b3q;
    int n0 = blockIdx.x * 32, k0 = blockIdx.y * 32;
    int tx = threadIdx.x, ty = threadIdx.y;
#pragma unroll
    for (int r = 0; r < 4; r++)
        t[ty + r * 8][tx] = W[(size_t)(k0 + ty + r * 8) * DD + n0 + tx];
    __syncthreads();
#pragma unroll
    for (int r = 0; r < 4; r++) {
        int n = n0 + ty + r * 8, k = k0 + tx;
        float v = t[tx][ty + r * 8];
        __nv_bfloat16 h = __float2bfloat16(v);
        __nv_bfloat16 l = __float2bfloat16(v - __bfloat162float(h));
        B3[(size_t)n * K3 + k]        = h;
        B3[(size_t)n * K3 + DD + k]   = h;
        B3[(size_t)n * K3 + 2*DD + k] = l;
    }
}

// ---------------------------------------------------------------------------
// mma.sync bf16 GEMM: C[4096,512] = A3[4096,1536] * B3[512,1536]^T, f32 acc
// ---------------------------------------------------------------------------
#define MT 128
#define NT 128
#define KT 64
#define NK 24
#define STG 32768u
#define NSTG 3
#define GEMM_SMEM (NSTG * STG)

__device__ __forceinline__ void load_tile(int tile, int stg,
                                          const char* Ab, const char* Bb,
                                          uint32_t sb, int tid) {
    size_t koff = (size_t)tile * (KT * 2);
    uint32_t sA = sb + (uint32_t)stg * STG;
    uint32_t sB = sA + 16384u;
#pragma unroll
    for (int c = 0; c < 4; c++) {
        int q = tid + c * 256;
        int r = q >> 3, col = (q & 7) * 16;
        cp16(sA + SWZ128(r * 128 + col), Ab + (size_t)r * (K3 * 2) + koff + col);
    }
#pragma unroll
    for (int c = 0; c < 4; c++) {
        int q = tid + c * 256;
        int r = q >> 3, col = (q & 7) * 16;
        cp16(sB + SWZ128(r * 128 + col), Bb + (size_t)r * (K3 * 2) + koff + col);
    }
}

__global__ __launch_bounds__(256, 2)
void gemm3() {
    extern __shared__ char smem[];
    uint32_t sb = smem_u32(smem);
    const int tid = threadIdx.x, wid = tid >> 5, lane = tid & 31;
    const int m0 = blockIdx.x * MT;
    const int n0 = blockIdx.y * NT;
    const __nv_bfloat16* B3 = blockIdx.z ? g_b3k : g_b3q;
    float* C = blockIdx.z ? g_k : g_q;

    const char* Ab = (const char*)g_a3 + (size_t)m0 * (K3 * 2);
    const char* Bb = (const char*)B3 + (size_t)n0 * (K3 * 2);

    const int wm = wid & 1;
    const int wn = wid >> 1;

    float acc[4][4][4];
#pragma unroll
    for (int i = 0; i < 4; i++)
#pragma unroll
        for (int j = 0; j < 4; j++)
#pragma unroll
            for (int r = 0; r < 4; r++) acc[i][j][r] = 0.f;

    load_tile(0, 0, Ab, Bb, sb, tid); CP_COMMIT();
    load_tile(1, 1, Ab, Bb, sb, tid); CP_COMMIT();

    const int a_row = wm * 64 + (lane & 15);
    const int a_cg  = (lane >> 4) * 16;
    const int b_row = wn * 32 + (lane & 7);
    const int b_cg  = ((lane >> 3) & 1) * 16;

    for (int t = 0; t < NK; t++) {
        asm volatile("cp.async.wait_group 1;" ::: "memory");
        __syncthreads();

        if (t + 2 < NK)
            load_tile(t + 2, (t + 2) % NSTG, Ab, Bb, sb, tid);
        CP_COMMIT();

        uint32_t sA = sb + (uint32_t)(t % NSTG) * STG;
        uint32_t sB = sA + 16384u;
#pragma unroll
        for (int ks = 0; ks < 4; ks++) {
            uint32_t af[4][4], bf[4][2];
#pragma unroll
            for (int mi = 0; mi < 4; mi++)
                ldm_x4(af[mi][0], af[mi][1], af[mi][2], af[mi][3],
                       sA + SWZ128((a_row + mi * 16) * 128 + ks * 32 + a_cg));
#pragma unroll
            for (int ni = 0; ni < 4; ni++)
                ldm_x2(bf[ni][0], bf[ni][1],
                       sB + SWZ128((b_row + ni * 8) * 128 + ks * 32 + b_cg));
#pragma unroll
            for (int mi = 0; mi < 4; mi++)
#pragma unroll
                for (int ni = 0; ni < 4; ni++)
                    mma16816(acc[mi][ni], af[mi], bf[ni]);
        }
    }

    const int er = lane >> 2;
    const int ec = (lane & 3) * 2;
#pragma unroll
    for (int mi = 0; mi < 4; mi++) {
        int r0 = m0 + wm * 64 + mi * 16 + er;
#pragma unroll
        for (int ni = 0; ni < 4; ni++) {
            int cc = n0 + wn * 32 + ni * 8 + ec;
            *(float2*)(C + (size_t)r0 * DD + cc) = make_float2(acc[mi][ni][0], acc[mi][ni][1]);
            *(float2*)(C + (size_t)(r0 + 8) * DD + cc) = make_float2(acc[mi][ni][2], acc[mi][ni][3]);
        }
    }
}

// ---------------------------------------------------------------------------
// wts: block = 16 consecutive i (512 thr), 30 k rows staged in smem.
// warp = one i; lane owns 16 floats of head (lane>>2).
// Writes scalar weights, TRANSPOSED layout [i][jj*8+h].
// ---------------------------------------------------------------------------
#define WTS_SMEM (30 * DD * 4)    // 61440

__global__ __launch_bounds__(512)
void wts() {
    extern __shared__ float sk[];           // [30][512], swizzled
    float4* sk4 = (float4*)sk;

    const int b = blockIdx.y;
    const int i0 = blockIdx.x * 16;
    const int tid = threadIdx.x;

    for (int idx = tid; idx < 30 * 128; idx += 512) {
        int r = idx >> 7, p = idx & 127;
        int j = i0 - LR + r;
        j = j < 0 ? 0 : (j >= SS ? SS - 1 : j);
        int ps = p ^ (((p >> 4) & 1) << 2);
        sk4[r * 128 + ps] = ((const float4*)(g_k + ((size_t)b * SS + j) * DD))[p];
    }
    __syncthreads();

    const int wid = tid >> 5, lane = tid & 31;
    const int i = i0 + wid;
    const int h = lane >> 2, g = lane & 3;
    const int flip = (h & 1) << 2;

    const float4* q4 = (const float4*)(g_q + ((size_t)b * SS + i) * DD);
    float4 ql[4];
#pragma unroll
    for (int t = 0; t < 4; t++) ql[t] = q4[16 * h + g + 4 * t];

    float sc[15];
#pragma unroll
    for (int jj = 0; jj < 15; jj++) {
        int j = i - LR + jj;
        bool valid = (j >= 0) && (j < SS);
        const float4* kr = sk4 + (wid + jj) * 128;
        float p = 0.f;
#pragma unroll
        for (int t = 0; t < 4; t++) {
            float4 kv = kr[(16 * h + g + 4 * t) ^ flip];
            p += ql[t].x * kv.x + ql[t].y * kv.y + ql[t].z * kv.z + ql[t].w * kv.w;
        }
        p += __shfl_xor_sync(0xffffffffu, p, 1);
        p += __shfl_xor_sync(0xffffffffu, p, 2);
        sc[jj] = valid ? p * 0.125f : -1e30f;
    }

    float m = -1e30f;
#pragma unroll
    for (int jj = 0; jj < 15; jj++) m = fmaxf(m, sc[jj]);
    float s = 0.f;
#pragma unroll
    for (int jj = 0; jj < 15; jj++) { sc[jj] = __expf(sc[jj] - m); s += sc[jj]; }
    float inv = 1.f / s;

    float* wp = g_w + (((size_t)b * SS + i) << 7);
#pragma unroll
    for (int jj = g; jj < 15; jj += 4)
        wp[jj * 8 + h] = sc[jj] * inv;
}

// ---------------------------------------------------------------------------
// ctx v6: out[b,h,i,:] = sum_jj w * hs[b, i-7+jj, :], scalar FFMA
// block = 32 i x 256 d; grid (64, 2, 2); 62 KB smem -> 2 CTAs/SM (128-reg cap,
// no spills -- the (256,3) 85-reg cap in v5 spilled and cost 2x)
// weights [il][jj*8+h] float in smem: per jj, 2x float4 broadcast loads
// ---------------------------------------------------------------------------
#define CTX_SMEM (46 * 256 * 4 + 32 * 128 * 4)   // 47104 + 16384 = 63488

__global__ __launch_bounds__(256, 2)
void ctx(const float* __restrict__ hs, float* __restrict__ out) {
    extern __shared__ char smemraw[];
    float* sh = (float*)smemraw;                          // [46][256]
    float* sw = (float*)(smemraw + 46 * 256 * 4);         // [32][128] (jj*8+h)

    const int ic = blockIdx.x, dc = blockIdx.y, b = blockIdx.z;
    const int i0 = ic * 32, d0 = dc * 256;
    const int tid = threadIdx.x;

    for (int idx = tid; idx < 46 * 64; idx += 256) {
        int r = idx >> 6, c = idx & 63;
        int j = i0 - LR + r;
        j = j < 0 ? 0 : (j >= SS ? SS - 1 : j);
        ((float4*)sh)[idx] = ((const float4*)(hs + ((size_t)b * SS + j) * DD + d0))[c];
    }
    {
        const float4* gw4 = (const float4*)(g_w + (((size_t)b * SS + i0) << 7));
        for (int idx = tid; idx < 1024; idx += 256)
            ((float4*)sw)[idx] = gw4[idx];
    }
    __syncthreads();

    const int wid = tid >> 5, lane = tid & 31;
    const float4* sh4 = (const float4*)sh;     // row stride 64 float4

#pragma unroll
    for (int ii = 0; ii < 4; ii++) {
        const int il = ii * 8 + wid;
        const int ig = i0 + il;
        const float* wp = &sw[il * 128];
#pragma unroll
        for (int cp = 0; cp < 2; cp++) {
            const int c4 = lane + 32 * cp;                 // float4 col 0..63
            float4 acc[HH];
#pragma unroll
            for (int h = 0; h < HH; h++) { acc[h].x = acc[h].y = acc[h].z = acc[h].w = 0.f; }
#pragma unroll
            for (int jj = 0; jj < 15; jj++) {
                float4 v = sh4[(il + jj) * 64 + c4];
                float4 wa = *(const float4*)(wp + jj * 8);       // heads 0..3
                float4 wb = *(const float4*)(wp + jj * 8 + 4);   // heads 4..7
                acc[0].x += wa.x * v.x; acc[0].y += wa.x * v.y; acc[0].z += wa.x * v.z; acc[0].w += wa.x * v.w;
                acc[1].x += wa.y * v.x; acc[1].y += wa.y * v.y; acc[1].z += wa.y * v.z; acc[1].w += wa.y * v.w;
                acc[2].x += wa.z * v.x; acc[2].y += wa.z * v.y; acc[2].z += wa.z * v.z; acc[2].w += wa.z * v.w;
                acc[3].x += wa.w * v.x; acc[3].y += wa.w * v.y; acc[3].z += wa.w * v.z; acc[3].w += wa.w * v.w;
                acc[4].x += wb.x * v.x; acc[4].y += wb.x * v.y; acc[4].z += wb.x * v.z; acc[4].w += wb.x * v.w;
                acc[5].x += wb.y * v.x; acc[5].y += wb.y * v.y; acc[5].z += wb.y * v.z; acc[5].w += wb.y * v.w;
                acc[6].x += wb.z * v.x; acc[6].y += wb.z * v.y; acc[6].z += wb.z * v.z; acc[6].w += wb.z * v.w;
                acc[7].x += wb.w * v.x; acc[7].y += wb.w * v.y; acc[7].z += wb.w * v.z; acc[7].w += wb.w * v.w;
            }
#pragma unroll
            for (int h = 0; h < HH; h++)
                *(float4*)(out + (((size_t)b * HH + h) * SS + ig) * DD + d0 + c4 * 4) = acc[h];
        }
    }
}

// ---------------------------------------------------------------------------
extern "C" void kernel_launch(void* const* d_in, const int* in_sizes, int n_in,
                              void* d_out, int out_size) {
    const float* hs = (const float*)d_in[0];
    const float* Wq = (const float*)d_in[1];
    const float* Wk = (const float*)d_in[2];
    float* out = (float*)d_out;

    cudaFuncSetAttribute(gemm3, cudaFuncAttributeMaxDynamicSharedMemorySize, GEMM_SMEM);
    cudaFuncSetAttribute(ctx, cudaFuncAttributeMaxDynamicSharedMemorySize, CTX_SMEM);
    cudaFuncSetAttribute(wts, cudaFuncAttributeMaxDynamicSharedMemorySize, WTS_SMEM);

    split_hs<<<2048, 256>>>(hs);
    split_w<<<dim3(16, 16, 2), dim3(32, 8)>>>(Wq, Wk);
    gemm3<<<dim3(32, 4, 2), 256, GEMM_SMEM>>>();
    wts<<<dim3(SS / 16, BB), 512, WTS_SMEM>>>();
    ctx<<<dim3(64, 2, 2), 256, CTX_SMEM>>>(hs, out);
}

// round 11
// speedup vs baseline: 1.5539x; 1.1606x over previous
#include <cuda_runtime.h>
#include <cuda_fp16.h>
#include <cstdint>

#define BB 2
#define SS 2048
#define DD 512
#define HH 8
#define LR 7
#define MTOT (BB*SS)        // 4096
#define K2 (2*DD)           // 1024

// scratch
__device__ float g_q[MTOT * DD];
__device__ float g_k[MTOT * DD];
__device__ float g_w[MTOT * 128];        // [b*S+i][jj*8+h] normalized band weights
__device__ __half g_a2[MTOT * K2];       // [hi | lo] along K
__device__ __half g_b2q[DD * K2];        // [hi | hi] along K, rows = n
__device__ __half g_b2k[DD * K2];

#define SWZ128(off) ((off) ^ (((off) >> 3) & 0x70))

__device__ __forceinline__ uint32_t smem_u32(const void* p) {
    uint32_t a;
    asm("{ .reg .u64 t; cvta.to.shared.u64 t, %1; cvt.u32.u64 %0, t; }" : "=r"(a) : "l"(p));
    return a;
}
__device__ __forceinline__ void cp16(uint32_t s, const void* g) {
    asm volatile("cp.async.cg.shared.global [%0], [%1], 16;" :: "r"(s), "l"(g));
}
#define CP_COMMIT() asm volatile("cp.async.commit_group;" ::: "memory")

__device__ __forceinline__ void ldm_x4(uint32_t& r0, uint32_t& r1, uint32_t& r2, uint32_t& r3, uint32_t a) {
    asm volatile("ldmatrix.sync.aligned.m8n8.x4.shared.b16 {%0,%1,%2,%3}, [%4];"
                 : "=r"(r0), "=r"(r1), "=r"(r2), "=r"(r3) : "r"(a));
}
__device__ __forceinline__ void ldm_x2(uint32_t& r0, uint32_t& r1, uint32_t a) {
    asm volatile("ldmatrix.sync.aligned.m8n8.x2.shared.b16 {%0,%1}, [%2];"
                 : "=r"(r0), "=r"(r1) : "r"(a));
}
__device__ __forceinline__ void mma16816(float* d, const uint32_t* a, const uint32_t* b) {
    asm volatile("mma.sync.aligned.m16n8k16.row.col.f32.f16.f16.f32 "
                 "{%0,%1,%2,%3}, {%4,%5,%6,%7}, {%8,%9}, {%0,%1,%2,%3};"
                 : "+f"(d[0]), "+f"(d[1]), "+f"(d[2]), "+f"(d[3])
                 : "r"(a[0]), "r"(a[1]), "r"(a[2]), "r"(a[3]), "r"(b[0]), "r"(b[1]));
}

// ---------------------------------------------------------------------------
// split hidden_states into fp16 hi/lo, doubled K layout [hi | lo]
// ---------------------------------------------------------------------------
__global__ void split_hs(const float* __restrict__ hs) {
    int idx = blockIdx.x * 256 + threadIdx.x;     // float4 index
    int m = idx >> 7;
    int c = idx & 127;
    float4 v = ((const float4*)hs)[idx];
    __half hx = __float2half(v.x), hy = __float2half(v.y);
    __half hz = __float2half(v.z), hw = __float2half(v.w);
    __half lx = __float2half(v.x - __half2float(hx));
    __half ly = __float2half(v.y - __half2float(hy));
    __half lz = __float2half(v.z - __half2float(hz));
    __half lw = __float2half(v.w - __half2float(hw));
    __half2 H0; H0.x = hx; H0.y = hy;
    __half2 H1; H1.x = hz; H1.y = hw;
    __half2 L0; L0.x = lx; L0.y = ly;
    __half2 L1; L1.x = lz; L1.y = lw;
    __half* p = g_a2 + (size_t)m * K2 + 4 * c;
    *(__half2*)(p)        = H0; *(__half2*)(p + 2)        = H1;
    *(__half2*)(p + DD)   = L0; *(__half2*)(p + DD + 2)   = L1;
}

// ---------------------------------------------------------------------------
// split + transpose W (stored [k, n]) into B2 [n, 2K] = [hi | hi]
// ---------------------------------------------------------------------------
__global__ void split_w(const float* __restrict__ Wq, const float* __restrict__ Wk) {
    __shared__ float t[32][33];
    const float* W = blockIdx.z ? Wk : Wq;
    __half* B2 = blockIdx.z ? g_b2k : g_b2q;
    int n0 = blockIdx.x * 32, k0 = blockIdx.y * 32;
    int tx = threadIdx.x, ty = threadIdx.y;           // (32, 8)
#pragma unroll
    for (int r = 0; r < 4; r++)
        t[ty + r * 8][tx] = W[(size_t)(k0 + ty + r * 8) * DD + n0 + tx];
    __syncthreads();
#pragma unroll
    for (int r = 0; r < 4; r++) {
        int n = n0 + ty + r * 8, k = k0 + tx;
        __half h = __float2half(t[tx][ty + r * 8]);
        B2[(size_t)n * K2 + k]      = h;
        B2[(size_t)n * K2 + DD + k] = h;
    }
}

// ---------------------------------------------------------------------------
// mma.sync fp16 GEMM: C[4096,512] = A2[4096,1024] * B2[512,1024]^T, f32 acc
// CTA tile 128x128, 8 warps of 64x32, K-tile 64, 3-stage cp.async pipeline
// ---------------------------------------------------------------------------
#define MT 128
#define NT 128
#define KT 64
#define NK 16          // 1024/64
#define STG 32768u
#define NSTG 3
#define GEMM_SMEM (NSTG * STG)

__device__ __forceinline__ void load_tile(int tile, int stg,
                                          const char* Ab, const char* Bb,
                                          uint32_t sb, int tid) {
    size_t koff = (size_t)tile * (KT * 2);
    uint32_t sA = sb + (uint32_t)stg * STG;
    uint32_t sB = sA + 16384u;
#pragma unroll
    for (int c = 0; c < 4; c++) {
        int q = tid + c * 256;
        int r = q >> 3, col = (q & 7) * 16;
        cp16(sA + SWZ128(r * 128 + col), Ab + (size_t)r * (K2 * 2) + koff + col);
    }
#pragma unroll
    for (int c = 0; c < 4; c++) {
        int q = tid + c * 256;
        int r = q >> 3, col = (q & 7) * 16;
        cp16(sB + SWZ128(r * 128 + col), Bb + (size_t)r * (K2 * 2) + koff + col);
    }
}

__global__ __launch_bounds__(256, 2)
void gemm2() {
    extern __shared__ char smem[];
    uint32_t sb = smem_u32(smem);
    const int tid = threadIdx.x, wid = tid >> 5, lane = tid & 31;
    const int m0 = blockIdx.x * MT;
    const int n0 = blockIdx.y * NT;
    const __half* B2 = blockIdx.z ? g_b2k : g_b2q;
    float* C = blockIdx.z ? g_k : g_q;

    const char* Ab = (const char*)g_a2 + (size_t)m0 * (K2 * 2);
    const char* Bb = (const char*)B2 + (size_t)n0 * (K2 * 2);

    const int wm = wid & 1;
    const int wn = wid >> 1;

    float acc[4][4][4];
#pragma unroll
    for (int i = 0; i < 4; i++)
#pragma unroll
        for (int j = 0; j < 4; j++)
#pragma unroll
            for (int r = 0; r < 4; r++) acc[i][j][r] = 0.f;

    load_tile(0, 0, Ab, Bb, sb, tid); CP_COMMIT();
    load_tile(1, 1, Ab, Bb, sb, tid); CP_COMMIT();

    const int a_row = wm * 64 + (lane & 15);
    const int a_cg  = (lane >> 4) * 16;
    const int b_row = wn * 32 + (lane & 7);
    const int b_cg  = ((lane >> 3) & 1) * 16;

    for (int t = 0; t < NK; t++) {
        asm volatile("cp.async.wait_group 1;" ::: "memory");
        __syncthreads();

        if (t + 2 < NK)
            load_tile(t + 2, (t + 2) % NSTG, Ab, Bb, sb, tid);
        CP_COMMIT();

        uint32_t sA = sb + (uint32_t)(t % NSTG) * STG;
        uint32_t sB = sA + 16384u;
#pragma unroll
        for (int ks = 0; ks < 4; ks++) {
            uint32_t af[4][4], bf[4][2];
#pragma unroll
            for (int mi = 0; mi < 4; mi++)
                ldm_x4(af[mi][0], af[mi][1], af[mi][2], af[mi][3],
                       sA + SWZ128((a_row + mi * 16) * 128 + ks * 32 + a_cg));
#pragma unroll
            for (int ni = 0; ni < 4; ni++)
                ldm_x2(bf[ni][0], bf[ni][1],
                       sB + SWZ128((b_row + ni * 8) * 128 + ks * 32 + b_cg));
#pragma unroll
            for (int mi = 0; mi < 4; mi++)
#pragma unroll
                for (int ni = 0; ni < 4; ni++)
                    mma16816(acc[mi][ni], af[mi], bf[ni]);
        }
    }

    const int er = lane >> 2;
    const int ec = (lane & 3) * 2;
#pragma unroll
    for (int mi = 0; mi < 4; mi++) {
        int r0 = m0 + wm * 64 + mi * 16 + er;
#pragma unroll
        for (int ni = 0; ni < 4; ni++) {
            int cc = n0 + wn * 32 + ni * 8 + ec;
            *(float2*)(C + (size_t)r0 * DD + cc) = make_float2(acc[mi][ni][0], acc[mi][ni][1]);
            *(float2*)(C + (size_t)(r0 + 8) * DD + cc) = make_float2(acc[mi][ni][2], acc[mi][ni][3]);
        }
    }
}

// ---------------------------------------------------------------------------
// wts: block = 16 consecutive i (512 thr), 30 k rows staged in smem.
// warp = one i; lane owns 16 floats of head (lane>>2).
// Writes scalar weights, TRANSPOSED layout [i][jj*8+h].
// ---------------------------------------------------------------------------
#define WTS_SMEM (30 * DD * 4)    // 61440

__global__ __launch_bounds__(512)
void wts() {
    extern __shared__ float sk[];           // [30][512], swizzled
    float4* sk4 = (float4*)sk;

    const int b = blockIdx.y;
    const int i0 = blockIdx.x * 16;
    const int tid = threadIdx.x;

    for (int idx = tid; idx < 30 * 128; idx += 512) {
        int r = idx >> 7, p = idx & 127;
        int j = i0 - LR + r;
        j = j < 0 ? 0 : (j >= SS ? SS - 1 : j);
        int ps = p ^ (((p >> 4) & 1) << 2);
        sk4[r * 128 + ps] = ((const float4*)(g_k + ((size_t)b * SS + j) * DD))[p];
    }
    __syncthreads();

    const int wid = tid >> 5, lane = tid & 31;
    const int i = i0 + wid;
    const int h = lane >> 2, g = lane & 3;
    const int flip = (h & 1) << 2;

    const float4* q4 = (const float4*)(g_q + ((size_t)b * SS + i) * DD);
    float4 ql[4];
#pragma unroll
    for (int t = 0; t < 4; t++) ql[t] = q4[16 * h + g + 4 * t];

    float sc[15];
#pragma unroll
    for (int jj = 0; jj < 15; jj++) {
        int j = i - LR + jj;
        bool valid = (j >= 0) && (j < SS);
        const float4* kr = sk4 + (wid + jj) * 128;
        float p = 0.f;
#pragma unroll
        for (int t = 0; t < 4; t++) {
            float4 kv = kr[(16 * h + g + 4 * t) ^ flip];
            p += ql[t].x * kv.x + ql[t].y * kv.y + ql[t].z * kv.z + ql[t].w * kv.w;
        }
        p += __shfl_xor_sync(0xffffffffu, p, 1);
        p += __shfl_xor_sync(0xffffffffu, p, 2);
        sc[jj] = valid ? p * 0.125f : -1e30f;
    }

    float m = -1e30f;
#pragma unroll
    for (int jj = 0; jj < 15; jj++) m = fmaxf(m, sc[jj]);
    float s = 0.f;
#pragma unroll
    for (int jj = 0; jj < 15; jj++) { sc[jj] = __expf(sc[jj] - m); s += sc[jj]; }
    float inv = 1.f / s;

    float* wp = g_w + (((size_t)b * SS + i) << 7);
#pragma unroll
    for (int jj = g; jj < 15; jj += 4)
        wp[jj * 8 + h] = sc[jj] * inv;
}

// ---------------------------------------------------------------------------
// ctx: out[b,h,i,:] = sum_jj w * hs[b, i-7+jj, :], scalar FFMA
// block = 32 i x 256 d; grid (64, 2, 2); 62 KB smem -> 2 CTAs/SM
// ---------------------------------------------------------------------------
#define CTX_SMEM (46 * 256 * 4 + 32 * 128 * 4)   // 63488

__global__ __launch_bounds__(256, 2)
void ctx(const float* __restrict__ hs, float* __restrict__ out) {
    extern __shared__ char smemraw[];
    float* sh = (float*)smemraw;                          // [46][256]
    float* sw = (float*)(smemraw + 46 * 256 * 4);         // [32][128] (jj*8+h)

    const int ic = blockIdx.x, dc = blockIdx.y, b = blockIdx.z;
    const int i0 = ic * 32, d0 = dc * 256;
    const int tid = threadIdx.x;

    for (int idx = tid; idx < 46 * 64; idx += 256) {
        int r = idx >> 6, c = idx & 63;
        int j = i0 - LR + r;
        j = j < 0 ? 0 : (j >= SS ? SS - 1 : j);
        ((float4*)sh)[idx] = ((const float4*)(hs + ((size_t)b * SS + j) * DD + d0))[c];
    }
    {
        const float4* gw4 = (const float4*)(g_w + (((size_t)b * SS + i0) << 7));
        for (int idx = tid; idx < 1024; idx += 256)
            ((float4*)sw)[idx] = gw4[idx];
    }
    __syncthreads();

    const int wid = tid >> 5, lane = tid & 31;
    const float4* sh4 = (const float4*)sh;     // row stride 64 float4

#pragma unroll
    for (int ii = 0; ii < 4; ii++) {
        const int il = ii * 8 + wid;
        const int ig = i0 + il;
        const float* wp = &sw[il * 128];
#pragma unroll
        for (int cp = 0; cp < 2; cp++) {
            const int c4 = lane + 32 * cp;                 // float4 col 0..63
            float4 acc[HH];
#pragma unroll
            for (int h = 0; h < HH; h++) { acc[h].x = acc[h].y = acc[h].z = acc[h].w = 0.f; }
#pragma unroll
            for (int jj = 0; jj < 15; jj++) {
                float4 v = sh4[(il + jj) * 64 + c4];
                float4 wa = *(const float4*)(wp + jj * 8);       // heads 0..3
                float4 wb = *(const float4*)(wp + jj * 8 + 4);   // heads 4..7
                acc[0].x += wa.x * v.x; acc[0].y += wa.x * v.y; acc[0].z += wa.x * v.z; acc[0].w += wa.x * v.w;
                acc[1].x += wa.y * v.x; acc[1].y += wa.y * v.y; acc[1].z += wa.y * v.z; acc[1].w += wa.y * v.w;
                acc[2].x += wa.z * v.x; acc[2].y += wa.z * v.y; acc[2].z += wa.z * v.z; acc[2].w += wa.z * v.w;
                acc[3].x += wa.w * v.x; acc[3].y += wa.w * v.y; acc[3].z += wa.w * v.z; acc[3].w += wa.w * v.w;
                acc[4].x += wb.x * v.x; acc[4].y += wb.x * v.y; acc[4].z += wb.x * v.z; acc[4].w += wb.x * v.w;
                acc[5].x += wb.y * v.x; acc[5].y += wb.y * v.y; acc[5].z += wb.y * v.z; acc[5].w += wb.y * v.w;
                acc[6].x += wb.z * v.x; acc[6].y += wb.z * v.y; acc[6].z += wb.z * v.z; acc[6].w += wb.z * v.w;
                acc[7].x += wb.w * v.x; acc[7].y += wb.w * v.y; acc[7].z += wb.w * v.z; acc[7].w += wb.w * v.w;
            }
#pragma unroll
            for (int h = 0; h < HH; h++)
                *(float4*)(out + (((size_t)b * HH + h) * SS + ig) * DD + d0 + c4 * 4) = acc[h];
        }
    }
}

// ---------------------------------------------------------------------------
extern "C" void kernel_launch(void* const* d_in, const int* in_sizes, int n_in,
                              void* d_out, int out_size) {
    const float* hs = (const float*)d_in[0];
    const float* Wq = (const float*)d_in[1];
    const float* Wk = (const float*)d_in[2];
    float* out = (float*)d_out;

    cudaFuncSetAttribute(gemm2, cudaFuncAttributeMaxDynamicSharedMemorySize, GEMM_SMEM);
    cudaFuncSetAttribute(ctx, cudaFuncAttributeMaxDynamicSharedMemorySize, CTX_SMEM);
    cudaFuncSetAttribute(wts, cudaFuncAttributeMaxDynamicSharedMemorySize, WTS_SMEM);

    split_hs<<<2048, 256>>>(hs);
    split_w<<<dim3(16, 16, 2), dim3(32, 8)>>>(Wq, Wk);
    gemm2<<<dim3(32, 4, 2), 256, GEMM_SMEM>>>();
    wts<<<dim3(SS / 16, BB), 512, WTS_SMEM>>>();
    ctx<<<dim3(64, 2, 2), 256, CTX_SMEM>>>(hs, out);
}

// round 12
// speedup vs baseline: 2.0180x; 1.2986x over previous
#include <cuda_runtime.h>
#include <cuda_fp16.h>
#include <cstdint>

#define BB 2
#define SS 2048
#define DD 512
#define HH 8
#define LR 7
#define MTOT (BB*SS)        // 4096
#define K2 (2*DD)           // 1024
#define NBLK (SS/16)        // 128 i-blocks per batch

// scratch
__device__ float g_q[MTOT * DD];
__device__ float g_k[MTOT * DD];
__device__ __half g_a2[MTOT * K2];       // [hi | lo] along K (hs fp16 pair)
__device__ __half g_b2q[DD * K2];        // [hi | hi] along K, rows = n
__device__ __half g_b2k[DD * K2];
__device__ __half g_wa[BB * NBLK * 128 * 32];  // per block: A = [128 r=(il,h)][32 jw] fp16, zero-padded band

#define SWZ128(off) ((off) ^ (((off) >> 3) & 0x70))

__device__ __forceinline__ uint32_t smem_u32(const void* p) {
    uint32_t a;
    asm("{ .reg .u64 t; cvta.to.shared.u64 t, %1; cvt.u32.u64 %0, t; }" : "=r"(a) : "l"(p));
    return a;
}
__device__ __forceinline__ void cp16(uint32_t s, const void* g) {
    asm volatile("cp.async.cg.shared.global [%0], [%1], 16;" :: "r"(s), "l"(g));
}
#define CP_COMMIT() asm volatile("cp.async.commit_group;" ::: "memory")

__device__ __forceinline__ void ldm_x4(uint32_t& r0, uint32_t& r1, uint32_t& r2, uint32_t& r3, uint32_t a) {
    asm volatile("ldmatrix.sync.aligned.m8n8.x4.shared.b16 {%0,%1,%2,%3}, [%4];"
                 : "=r"(r0), "=r"(r1), "=r"(r2), "=r"(r3) : "r"(a));
}
__device__ __forceinline__ void ldm_x2(uint32_t& r0, uint32_t& r1, uint32_t a) {
    asm volatile("ldmatrix.sync.aligned.m8n8.x2.shared.b16 {%0,%1}, [%2];"
                 : "=r"(r0), "=r"(r1) : "r"(a));
}
__device__ __forceinline__ void ldm_x2t(uint32_t& r0, uint32_t& r1, uint32_t a) {
    asm volatile("ldmatrix.sync.aligned.m8n8.x2.trans.shared.b16 {%0,%1}, [%2];"
                 : "=r"(r0), "=r"(r1) : "r"(a));
}
__device__ __forceinline__ void mma16816(float* d, const uint32_t* a, const uint32_t* b) {
    asm volatile("mma.sync.aligned.m16n8k16.row.col.f32.f16.f16.f32 "
                 "{%0,%1,%2,%3}, {%4,%5,%6,%7}, {%8,%9}, {%0,%1,%2,%3};"
                 : "+f"(d[0]), "+f"(d[1]), "+f"(d[2]), "+f"(d[3])
                 : "r"(a[0]), "r"(a[1]), "r"(a[2]), "r"(a[3]), "r"(b[0]), "r"(b[1]));
}

// ---------------------------------------------------------------------------
// split hidden_states into fp16 hi/lo, doubled K layout [hi | lo]
// ---------------------------------------------------------------------------
__global__ void split_hs(const float* __restrict__ hs) {
    int idx = blockIdx.x * 256 + threadIdx.x;
    int m = idx >> 7;
    int c = idx & 127;
    float4 v = ((const float4*)hs)[idx];
    __half hx = __float2half(v.x), hy = __float2half(v.y);
    __half hz = __float2half(v.z), hw = __float2half(v.w);
    __half lx = __float2half(v.x - __half2float(hx));
    __half ly = __float2half(v.y - __half2float(hy));
    __half lz = __float2half(v.z - __half2float(hz));
    __half lw = __float2half(v.w - __half2float(hw));
    __half2 H0; H0.x = hx; H0.y = hy;
    __half2 H1; H1.x = hz; H1.y = hw;
    __half2 L0; L0.x = lx; L0.y = ly;
    __half2 L1; L1.x = lz; L1.y = lw;
    __half* p = g_a2 + (size_t)m * K2 + 4 * c;
    *(__half2*)(p)        = H0; *(__half2*)(p + 2)        = H1;
    *(__half2*)(p + DD)   = L0; *(__half2*)(p + DD + 2)   = L1;
}

// ---------------------------------------------------------------------------
// split + transpose W (stored [k, n]) into B2 [n, 2K] = [hi | hi]
// ---------------------------------------------------------------------------
__global__ void split_w(const float* __restrict__ Wq, const float* __restrict__ Wk) {
    __shared__ float t[32][33];
    const float* W = blockIdx.z ? Wk : Wq;
    __half* B2 = blockIdx.z ? g_b2k : g_b2q;
    int n0 = blockIdx.x * 32, k0 = blockIdx.y * 32;
    int tx = threadIdx.x, ty = threadIdx.y;
#pragma unroll
    for (int r = 0; r < 4; r++)
        t[ty + r * 8][tx] = W[(size_t)(k0 + ty + r * 8) * DD + n0 + tx];
    __syncthreads();
#pragma unroll
    for (int r = 0; r < 4; r++) {
        int n = n0 + ty + r * 8, k = k0 + tx;
        __half h = __float2half(t[tx][ty + r * 8]);
        B2[(size_t)n * K2 + k]      = h;
        B2[(size_t)n * K2 + DD + k] = h;
    }
}

// ---------------------------------------------------------------------------
// mma.sync fp16 GEMM: C[4096,512] = A2 * B2^T, f32 acc (unchanged from R11)
// ---------------------------------------------------------------------------
#define MT 128
#define NT 128
#define KT 64
#define NK 16
#define STG 32768u
#define NSTG 3
#define GEMM_SMEM (NSTG * STG)

__device__ __forceinline__ void load_tile(int tile, int stg,
                                          const char* Ab, const char* Bb,
                                          uint32_t sb, int tid) {
    size_t koff = (size_t)tile * (KT * 2);
    uint32_t sA = sb + (uint32_t)stg * STG;
    uint32_t sB = sA + 16384u;
#pragma unroll
    for (int c = 0; c < 4; c++) {
        int q = tid + c * 256;
        int r = q >> 3, col = (q & 7) * 16;
        cp16(sA + SWZ128(r * 128 + col), Ab + (size_t)r * (K2 * 2) + koff + col);
    }
#pragma unroll
    for (int c = 0; c < 4; c++) {
        int q = tid + c * 256;
        int r = q >> 3, col = (q & 7) * 16;
        cp16(sB + SWZ128(r * 128 + col), Bb + (size_t)r * (K2 * 2) + koff + col);
    }
}

__global__ __launch_bounds__(256, 2)
void gemm2() {
    extern __shared__ char smem[];
    uint32_t sb = smem_u32(smem);
    const int tid = threadIdx.x, wid = tid >> 5, lane = tid & 31;
    const int m0 = blockIdx.x * MT;
    const int n0 = blockIdx.y * NT;
    const __half* B2 = blockIdx.z ? g_b2k : g_b2q;
    float* C = blockIdx.z ? g_k : g_q;

    const char* Ab = (const char*)g_a2 + (size_t)m0 * (K2 * 2);
    const char* Bb = (const char*)B2 + (size_t)n0 * (K2 * 2);

    const int wm = wid & 1;
    const int wn = wid >> 1;

    float acc[4][4][4];
#pragma unroll
    for (int i = 0; i < 4; i++)
#pragma unroll
        for (int j = 0; j < 4; j++)
#pragma unroll
            for (int r = 0; r < 4; r++) acc[i][j][r] = 0.f;

    load_tile(0, 0, Ab, Bb, sb, tid); CP_COMMIT();
    load_tile(1, 1, Ab, Bb, sb, tid); CP_COMMIT();

    const int a_row = wm * 64 + (lane & 15);
    const int a_cg  = (lane >> 4) * 16;
    const int b_row = wn * 32 + (lane & 7);
    const int b_cg  = ((lane >> 3) & 1) * 16;

    for (int t = 0; t < NK; t++) {
        asm volatile("cp.async.wait_group 1;" ::: "memory");
        __syncthreads();

        if (t + 2 < NK)
            load_tile(t + 2, (t + 2) % NSTG, Ab, Bb, sb, tid);
        CP_COMMIT();

        uint32_t sA = sb + (uint32_t)(t % NSTG) * STG;
        uint32_t sB = sA + 16384u;
#pragma unroll
        for (int ks = 0; ks < 4; ks++) {
            uint32_t af[4][4], bf[4][2];
#pragma unroll
            for (int mi = 0; mi < 4; mi++)
                ldm_x4(af[mi][0], af[mi][1], af[mi][2], af[mi][3],
                       sA + SWZ128((a_row + mi * 16) * 128 + ks * 32 + a_cg));
#pragma unroll
            for (int ni = 0; ni < 4; ni++)
                ldm_x2(bf[ni][0], bf[ni][1],
                       sB + SWZ128((b_row + ni * 8) * 128 + ks * 32 + b_cg));
#pragma unroll
            for (int mi = 0; mi < 4; mi++)
#pragma unroll
                for (int ni = 0; ni < 4; ni++)
                    mma16816(acc[mi][ni], af[mi], bf[ni]);
        }
    }

    const int er = lane >> 2;
    const int ec = (lane & 3) * 2;
#pragma unroll
    for (int mi = 0; mi < 4; mi++) {
        int r0 = m0 + wm * 64 + mi * 16 + er;
#pragma unroll
        for (int ni = 0; ni < 4; ni++) {
            int cc = n0 + wn * 32 + ni * 8 + ec;
            *(float2*)(C + (size_t)r0 * DD + cc) = make_float2(acc[mi][ni][0], acc[mi][ni][1]);
            *(float2*)(C + (size_t)(r0 + 8) * DD + cc) = make_float2(acc[mi][ni][2], acc[mi][ni][3]);
        }
    }
}

// ---------------------------------------------------------------------------
// wts: band softmax -> fp16 zero-padded A blocks g_wa [blk][128 r][32 jw]
// block = 16 consecutive i (512 thr), 30 k rows staged in smem.
// ---------------------------------------------------------------------------
#define WTS_SMEM ((30 * DD + 16 * 8 * 16) * 4)    // 61440 + 8192 = 69632

__global__ __launch_bounds__(512)
void wts() {
    extern __shared__ float sk[];            // [30][512] swizzled, then ws[16][8][16]
    float4* sk4 = (float4*)sk;
    float* ws = sk + 30 * DD;

    const int b = blockIdx.y;
    const int blk = blockIdx.x;
    const int i0 = blk * 16;
    const int tid = threadIdx.x;

    for (int idx = tid; idx < 30 * 128; idx += 512) {
        int r = idx >> 7, p = idx & 127;
        int j = i0 - LR + r;
        j = j < 0 ? 0 : (j >= SS ? SS - 1 : j);
        int ps = p ^ (((p >> 4) & 1) << 2);
        sk4[r * 128 + ps] = ((const float4*)(g_k + ((size_t)b * SS + j) * DD))[p];
    }
    __syncthreads();

    const int wid = tid >> 5, lane = tid & 31;
    const int i = i0 + wid;
    const int h = lane >> 2, g = lane & 3;
    const int flip = (h & 1) << 2;

    const float4* q4 = (const float4*)(g_q + ((size_t)b * SS + i) * DD);
    float4 ql[4];
#pragma unroll
    for (int t = 0; t < 4; t++) ql[t] = q4[16 * h + g + 4 * t];

    float sc[15];
#pragma unroll
    for (int jj = 0; jj < 15; jj++) {
        int j = i - LR + jj;
        bool valid = (j >= 0) && (j < SS);
        const float4* kr = sk4 + (wid + jj) * 128;
        float p = 0.f;
#pragma unroll
        for (int t = 0; t < 4; t++) {
            float4 kv = kr[(16 * h + g + 4 * t) ^ flip];
            p += ql[t].x * kv.x + ql[t].y * kv.y + ql[t].z * kv.z + ql[t].w * kv.w;
        }
        p += __shfl_xor_sync(0xffffffffu, p, 1);
        p += __shfl_xor_sync(0xffffffffu, p, 2);
        sc[jj] = valid ? p * 0.125f : -1e30f;
    }

    float m = -1e30f;
#pragma unroll
    for (int jj = 0; jj < 15; jj++) m = fmaxf(m, sc[jj]);
    float s = 0.f;
#pragma unroll
    for (int jj = 0; jj < 15; jj++) { sc[jj] = __expf(sc[jj] - m); s += sc[jj]; }
    float inv = 1.f / s;

    // lane g==0 of each quad publishes the 15 weights for (il=wid, h)
    if (g == 0) {
        float* wrow = ws + (wid * 8 + h) * 16;
#pragma unroll
        for (int jj = 0; jj < 15; jj++) wrow[jj] = sc[jj] * inv;
        wrow[15] = 0.f;
    }
    __syncthreads();

    // cooperative write of zero-padded fp16 A block [128 r][32 jw]
    {
        int r = tid >> 2;                 // 0..127
        int cs = (tid & 3) * 8;           // col start
        int il = r >> 3;
        const float* wrow = ws + r * 16;  // (il,h) row
        unsigned pk[4];
#pragma unroll
        for (int p2 = 0; p2 < 4; p2++) {
            float v0 = 0.f, v1 = 0.f;
            int c0 = cs + p2 * 2, c1 = c0 + 1;
            int j0 = c0 - il, j1 = c1 - il;
            if (j0 >= 0 && j0 < 15) v0 = wrow[j0];
            if (j1 >= 0 && j1 < 15) v1 = wrow[j1];
            __half2 hh = __floats2half2_rn(v0, v1);
            pk[p2] = *reinterpret_cast<unsigned*>(&hh);
        }
        uint4 u; u.x = pk[0]; u.y = pk[1]; u.z = pk[2]; u.w = pk[3];
        *(uint4*)(g_wa + ((size_t)(b * NBLK + blk)) * 4096 + r * 32 + cs) = u;
    }
}

// ---------------------------------------------------------------------------
// ctxmma: out[b,h,i,:] = sum_j w * hs  as tensor-core GEMM per 16-i block
// A [128 r=(il,h)][K=64: (ks&1) reuses 32-col band], B [64 k][512 d] =
// [hs_hi window | hs_lo window] fp16. grid (128, 2); 75KB smem, 2 CTAs/SM.
// ---------------------------------------------------------------------------
#define CTXM_SMEM (65536 + 128 * 80)    // B 64KB + A 10KB = 75776

__global__ __launch_bounds__(256, 2)
void ctxmma(float* __restrict__ out) {
    extern __shared__ char smemraw[];
    uint32_t Bb = smem_u32(smemraw);           // B: 64 rows x 1024B, unit-swizzled
    uint32_t Ab = Bb + 65536;                  // A: 128 rows x 80B (stride 5 units)
    const int blk = blockIdx.x, b = blockIdx.y;
    const int i0 = blk * 16;
    const int tid = threadIdx.x, wid = tid >> 5, lane = tid & 31;

    // stage B: rows 0-31 = hs_hi[j], rows 32-63 = hs_lo[j], j = i0-7+r
    {
        const char* a2 = (const char*)g_a2 + (size_t)b * SS * (K2 * 2);
#pragma unroll
        for (int it = 0; it < 16; it++) {
            int idx = tid + it * 256;
            int r = idx >> 6, cu = idx & 63;
            int j = i0 - LR + (r & 31);
            j = j < 0 ? 0 : (j >= SS ? SS - 1 : j);
            const char* src = a2 + (size_t)j * (K2 * 2) + (r >> 5) * 1024 + cu * 16;
            cp16(Bb + r * 1024 + ((cu ^ (r & 7)) << 4), src);
        }
    }
    // stage A: 128 rows x 4 units, padded to stride 5 units
    {
        const char* wa = (const char*)g_wa + (size_t)(b * NBLK + blk) * 8192;
#pragma unroll
        for (int it = 0; it < 2; it++) {
            int idx = tid + it * 256;
            int r = idx >> 2, cu = idx & 3;
            cp16(Ab + r * 80 + cu * 16, wa + r * 64 + cu * 16);
        }
    }
    CP_COMMIT();
    asm volatile("cp.async.wait_group 0;" ::: "memory");
    __syncthreads();

    const int wm = wid & 1, wn = wid >> 1;
    const int er = lane >> 2, ec = (lane & 3) * 2;
    const int arow = wm * 64 + (lane & 15);
    const int acg  = ((lane >> 4) & 1) * 16;

#pragma unroll
    for (int dp = 0; dp < 4; dp++) {
        const int n0 = dp * 128 + wn * 32;
        float acc[4][4][4];
#pragma unroll
        for (int mi = 0; mi < 4; mi++)
#pragma unroll
            for (int ni = 0; ni < 4; ni++)
#pragma unroll
                for (int r = 0; r < 4; r++) acc[mi][ni][r] = 0.f;

#pragma unroll
        for (int ks = 0; ks < 4; ks++) {
            uint32_t af[4][4], bf[4][2];
#pragma unroll
            for (int mi = 0; mi < 4; mi++)
                ldm_x4(af[mi][0], af[mi][1], af[mi][2], af[mi][3],
                       Ab + (arow + mi * 16) * 80 + (ks & 1) * 32 + acg);
#pragma unroll
            for (int ni = 0; ni < 4; ni++) {
                int kr = ks * 16 + (lane & 15);
                int cu = (n0 + ni * 8) >> 3;
                ldm_x2t(bf[ni][0], bf[ni][1],
                        Bb + kr * 1024 + ((cu ^ (kr & 7)) << 4));
            }
#pragma unroll
            for (int mi = 0; mi < 4; mi++)
#pragma unroll
                for (int ni = 0; ni < 4; ni++)
                    mma16816(acc[mi][ni], af[mi], bf[ni]);
        }

        // epilogue: rows r=(il,h) scatter to out[b][h][i0+il][d]
#pragma unroll
        for (int mi = 0; mi < 4; mi++) {
            int r0 = wm * 64 + mi * 16 + er;
            int r1 = r0 + 8;
            int il0 = r0 >> 3, h0 = r0 & 7;
            int il1 = r1 >> 3, h1 = r1 & 7;
            float* o0 = out + (((size_t)b * HH + h0) * SS + i0 + il0) * DD;
            float* o1 = out + (((size_t)b * HH + h1) * SS + i0 + il1) * DD;
#pragma unroll
            for (int ni = 0; ni < 4; ni++) {
                int d = n0 + ni * 8 + ec;
                *(float2*)(o0 + d) = make_float2(acc[mi][ni][0], acc[mi][ni][1]);
                *(float2*)(o1 + d) = make_float2(acc[mi][ni][2], acc[mi][ni][3]);
            }
        }
    }
}

// ---------------------------------------------------------------------------
extern "C" void kernel_launch(void* const* d_in, const int* in_sizes, int n_in,
                              void* d_out, int out_size) {
    const float* hs = (const float*)d_in[0];
    const float* Wq = (const float*)d_in[1];
    const float* Wk = (const float*)d_in[2];
    float* out = (float*)d_out;

    cudaFuncSetAttribute(gemm2, cudaFuncAttributeMaxDynamicSharedMemorySize, GEMM_SMEM);
    cudaFuncSetAttribute(wts, cudaFuncAttributeMaxDynamicSharedMemorySize, WTS_SMEM);
    cudaFuncSetAttribute(ctxmma, cudaFuncAttributeMaxDynamicSharedMemorySize, CTXM_SMEM);

    split_hs<<<2048, 256>>>(hs);
    split_w<<<dim3(16, 16, 2), dim3(32, 8)>>>(Wq, Wk);
    gemm2<<<dim3(32, 4, 2), 256, GEMM_SMEM>>>();
    wts<<<dim3(NBLK, BB), 512, WTS_SMEM>>>();
    ctxmma<<<dim3(NBLK, BB), 256, CTXM_SMEM>>>(out);
}

// round 13
// speedup vs baseline: 2.2337x; 1.1069x over previous
#include <cuda_runtime.h>
#include <cuda_fp16.h>
#include <cstdint>

#define BB 2
#define SS 2048
#define DD 512
#define HH 8
#define LR 7
#define MTOT (BB*SS)        // 4096
#define K2 (2*DD)           // 1024
#define NBLK (SS/16)        // 128 i-blocks per batch

// scratch
__device__ __half g_qh[MTOT * DD];       // q projection, fp16
__device__ __half g_kh[MTOT * DD];       // k projection, fp16
__device__ __half g_a2[MTOT * K2];       // hs [hi | lo] along K
__device__ __half g_b2q[DD * K2];        // Wq^T [hi | hi], rows = n
__device__ __half g_b2k[DD * DD];        // Wk^T [hi] single, rows = n
__device__ __half g_wa[BB * NBLK * 128 * 32];  // A blocks for ctxmma

#define SWZ128(off) ((off) ^ (((off) >> 3) & 0x70))

__device__ __forceinline__ uint32_t smem_u32(const void* p) {
    uint32_t a;
    asm("{ .reg .u64 t; cvta.to.shared.u64 t, %1; cvt.u32.u64 %0, t; }" : "=r"(a) : "l"(p));
    return a;
}
__device__ __forceinline__ void cp16(uint32_t s, const void* g) {
    asm volatile("cp.async.cg.shared.global [%0], [%1], 16;" :: "r"(s), "l"(g));
}
#define CP_COMMIT() asm volatile("cp.async.commit_group;" ::: "memory")

__device__ __forceinline__ void ldm_x4(uint32_t& r0, uint32_t& r1, uint32_t& r2, uint32_t& r3, uint32_t a) {
    asm volatile("ldmatrix.sync.aligned.m8n8.x4.shared.b16 {%0,%1,%2,%3}, [%4];"
                 : "=r"(r0), "=r"(r1), "=r"(r2), "=r"(r3) : "r"(a));
}
__device__ __forceinline__ void ldm_x2(uint32_t& r0, uint32_t& r1, uint32_t a) {
    asm volatile("ldmatrix.sync.aligned.m8n8.x2.shared.b16 {%0,%1}, [%2];"
                 : "=r"(r0), "=r"(r1) : "r"(a));
}
__device__ __forceinline__ void ldm_x2t(uint32_t& r0, uint32_t& r1, uint32_t a) {
    asm volatile("ldmatrix.sync.aligned.m8n8.x2.trans.shared.b16 {%0,%1}, [%2];"
                 : "=r"(r0), "=r"(r1) : "r"(a));
}
__device__ __forceinline__ void mma16816(float* d, const uint32_t* a, const uint32_t* b) {
    asm volatile("mma.sync.aligned.m16n8k16.row.col.f32.f16.f16.f32 "
                 "{%0,%1,%2,%3}, {%4,%5,%6,%7}, {%8,%9}, {%0,%1,%2,%3};"
                 : "+f"(d[0]), "+f"(d[1]), "+f"(d[2]), "+f"(d[3])
                 : "r"(a[0]), "r"(a[1]), "r"(a[2]), "r"(a[3]), "r"(b[0]), "r"(b[1]));
}
__device__ __forceinline__ void unpack8(uint4 v, float* f) {
    const __half2* hp = (const __half2*)&v;
#pragma unroll
    for (int i = 0; i < 4; i++) {
        float2 x = __half22float2(hp[i]);
        f[2*i] = x.x; f[2*i+1] = x.y;
    }
}

// ---------------------------------------------------------------------------
// split hidden_states into fp16 hi/lo, doubled K layout [hi | lo]
// ---------------------------------------------------------------------------
__global__ void split_hs(const float* __restrict__ hs) {
    int idx = blockIdx.x * 256 + threadIdx.x;
    int m = idx >> 7;
    int c = idx & 127;
    float4 v = ((const float4*)hs)[idx];
    __half hx = __float2half(v.x), hy = __float2half(v.y);
    __half hz = __float2half(v.z), hw = __float2half(v.w);
    __half lx = __float2half(v.x - __half2float(hx));
    __half ly = __float2half(v.y - __half2float(hy));
    __half lz = __float2half(v.z - __half2float(hz));
    __half lw = __float2half(v.w - __half2float(hw));
    __half2 H0; H0.x = hx; H0.y = hy;
    __half2 H1; H1.x = hz; H1.y = hw;
    __half2 L0; L0.x = lx; L0.y = ly;
    __half2 L1; L1.x = lz; L1.y = lw;
    __half* p = g_a2 + (size_t)m * K2 + 4 * c;
    *(__half2*)(p)        = H0; *(__half2*)(p + 2)        = H1;
    *(__half2*)(p + DD)   = L0; *(__half2*)(p + DD + 2)   = L1;
}

// ---------------------------------------------------------------------------
// split + transpose W (stored [k, n]); Wq -> [hi|hi] K=1024, Wk -> [hi] K=512
// ---------------------------------------------------------------------------
__global__ void split_w(const float* __restrict__ Wq, const float* __restrict__ Wk) {
    __shared__ float t[32][33];
    const float* W = blockIdx.z ? Wk : Wq;
    int n0 = blockIdx.x * 32, k0 = blockIdx.y * 32;
    int tx = threadIdx.x, ty = threadIdx.y;
#pragma unroll
    for (int r = 0; r < 4; r++)
        t[ty + r * 8][tx] = W[(size_t)(k0 + ty + r * 8) * DD + n0 + tx];
    __syncthreads();
#pragma unroll
    for (int r = 0; r < 4; r++) {
        int n = n0 + ty + r * 8, k = k0 + tx;
        __half h = __float2half(t[tx][ty + r * 8]);
        if (blockIdx.z == 0) {
            g_b2q[(size_t)n * K2 + k]      = h;
            g_b2q[(size_t)n * K2 + DD + k] = h;
        } else {
            g_b2k[(size_t)n * DD + k] = h;
        }
    }
}

// ---------------------------------------------------------------------------
// mma.sync fp16 GEMM: q (K=1024) and k (K=512), fp16 output
// CTA tile 128x128, 8 warps of 64x32, K-tile 64, 3-stage cp.async pipeline
// ---------------------------------------------------------------------------
#define MT 128
#define NT 128
#define KT 64
#define STG 32768u
#define NSTG 3
#define GEMM_SMEM (NSTG * STG)

__device__ __forceinline__ void load_tile(int tile, int stg,
                                          const char* Ab, const char* Bb,
                                          size_t brow, uint32_t sb, int tid) {
    size_t koff = (size_t)tile * 128;    // KT halfs = 128 bytes
    uint32_t sA = sb + (uint32_t)stg * STG;
    uint32_t sB = sA + 16384u;
#pragma unroll
    for (int c = 0; c < 4; c++) {
        int q = tid + c * 256;
        int r = q >> 3, col = (q & 7) * 16;
        cp16(sA + SWZ128(r * 128 + col), Ab + (size_t)r * 2048 + koff + col);
    }
#pragma unroll
    for (int c = 0; c < 4; c++) {
        int q = tid + c * 256;
        int r = q >> 3, col = (q & 7) * 16;
        cp16(sB + SWZ128(r * 128 + col), Bb + (size_t)r * brow + koff + col);
    }
}

__global__ __launch_bounds__(256, 2)
void gemm2() {
    extern __shared__ char smem[];
    uint32_t sb = smem_u32(smem);
    const int tid = threadIdx.x, wid = tid >> 5, lane = tid & 31;
    const int m0 = blockIdx.x * MT;
    const int n0 = blockIdx.y * NT;

    const __half* B2 = blockIdx.z ? g_b2k : g_b2q;
    __half* C       = blockIdx.z ? g_kh : g_qh;
    const int nk    = blockIdx.z ? 8 : 16;
    const size_t brow = blockIdx.z ? 1024 : 2048;

    const char* Ab = (const char*)g_a2 + (size_t)m0 * 2048;
    const char* Bb = (const char*)B2 + (size_t)n0 * brow;

    const int wm = wid & 1;
    const int wn = wid >> 1;

    float acc[4][4][4];
#pragma unroll
    for (int i = 0; i < 4; i++)
#pragma unroll
        for (int j = 0; j < 4; j++)
#pragma unroll
            for (int r = 0; r < 4; r++) acc[i][j][r] = 0.f;

    load_tile(0, 0, Ab, Bb, brow, sb, tid); CP_COMMIT();
    load_tile(1, 1, Ab, Bb, brow, sb, tid); CP_COMMIT();

    const int a_row = wm * 64 + (lane & 15);
    const int a_cg  = (lane >> 4) * 16;
    const int b_row = wn * 32 + (lane & 7);
    const int b_cg  = ((lane >> 3) & 1) * 16;

    for (int t = 0; t < nk; t++) {
        asm volatile("cp.async.wait_group 1;" ::: "memory");
        __syncthreads();

        if (t + 2 < nk)
            load_tile(t + 2, (t + 2) % NSTG, Ab, Bb, brow, sb, tid);
        CP_COMMIT();

        uint32_t sA = sb + (uint32_t)(t % NSTG) * STG;
        uint32_t sB = sA + 16384u;
#pragma unroll
        for (int ks = 0; ks < 4; ks++) {
            uint32_t af[4][4], bf[4][2];
#pragma unroll
            for (int mi = 0; mi < 4; mi++)
                ldm_x4(af[mi][0], af[mi][1], af[mi][2], af[mi][3],
                       sA + SWZ128((a_row + mi * 16) * 128 + ks * 32 + a_cg));
#pragma unroll
            for (int ni = 0; ni < 4; ni++)
                ldm_x2(bf[ni][0], bf[ni][1],
                       sB + SWZ128((b_row + ni * 8) * 128 + ks * 32 + b_cg));
#pragma unroll
            for (int mi = 0; mi < 4; mi++)
#pragma unroll
                for (int ni = 0; ni < 4; ni++)
                    mma16816(acc[mi][ni], af[mi], bf[ni]);
        }
    }

    const int er = lane >> 2;
    const int ec = (lane & 3) * 2;
#pragma unroll
    for (int mi = 0; mi < 4; mi++) {
        int r0 = m0 + wm * 64 + mi * 16 + er;
#pragma unroll
        for (int ni = 0; ni < 4; ni++) {
            int cc = n0 + wn * 32 + ni * 8 + ec;
            __half2 v01 = __floats2half2_rn(acc[mi][ni][0], acc[mi][ni][1]);
            __half2 v23 = __floats2half2_rn(acc[mi][ni][2], acc[mi][ni][3]);
            *(__half2*)(C + (size_t)r0 * DD + cc) = v01;
            *(__half2*)(C + (size_t)(r0 + 8) * DD + cc) = v23;
        }
    }
}

// ---------------------------------------------------------------------------
// wts: band softmax from fp16 q/k -> fp16 zero-padded A blocks g_wa
// block = 16 consecutive i (512 thr); 30 k rows staged in smem (30KB, fp16,
// unit-XOR swizzle for conflict-free LDS.128).
// ---------------------------------------------------------------------------
#define WTS_SMEM (30 * DD * 2 + 16 * 8 * 16 * 4)    // 30720 + 8192 = 38912

__global__ __launch_bounds__(512, 2)
void wts() {
    extern __shared__ char smemraw[];
    uint4* sk4 = (uint4*)smemraw;                 // [30][64] units
    float* ws = (float*)(smemraw + 30 * DD * 2);  // [16][8][16]

    const int b = blockIdx.y;
    const int blk = blockIdx.x;
    const int i0 = blk * 16;
    const int tid = threadIdx.x;

    for (int idx = tid; idx < 30 * 64; idx += 512) {
        int r = idx >> 6, u = idx & 63;
        int us = u ^ ((u >> 3) & 7);
        int j = i0 - LR + r;
        j = j < 0 ? 0 : (j >= SS ? SS - 1 : j);
        sk4[r * 64 + us] = ((const uint4*)(g_kh + ((size_t)b * SS + j) * DD))[u];
    }
    __syncthreads();

    const int wid = tid >> 5, lane = tid & 31;
    const int i = i0 + wid;
    const int h = lane >> 2, g = lane & 3;

    // q slice: 16 halfs of head h, converted once to fp32 registers
    const __half* qrow = g_qh + ((size_t)b * SS + i) * DD + h * 64 + g * 16;
    float qf[16];
    unpack8(*(const uint4*)qrow, qf);
    unpack8(*(const uint4*)(qrow + 8), qf + 8);

    const int u0 = 8 * h + 2 * g;
    const int us0 = u0 ^ h;
    const int us1 = (u0 + 1) ^ h;

    float sc[15];
#pragma unroll
    for (int jj = 0; jj < 15; jj++) {
        int j = i - LR + jj;
        bool valid = (j >= 0) && (j < SS);
        const uint4* kr = sk4 + (wid + jj) * 64;
        float kf[16];
        unpack8(kr[us0], kf);
        unpack8(kr[us1], kf + 8);
        float p = 0.f;
#pragma unroll
        for (int t = 0; t < 16; t++) p += qf[t] * kf[t];
        p += __shfl_xor_sync(0xffffffffu, p, 1);
        p += __shfl_xor_sync(0xffffffffu, p, 2);
        sc[jj] = valid ? p * 0.125f : -1e30f;
    }

    float m = -1e30f;
#pragma unroll
    for (int jj = 0; jj < 15; jj++) m = fmaxf(m, sc[jj]);
    float s = 0.f;
#pragma unroll
    for (int jj = 0; jj < 15; jj++) { sc[jj] = __expf(sc[jj] - m); s += sc[jj]; }
    float inv = 1.f / s;

    if (g == 0) {
        float* wrow = ws + (wid * 8 + h) * 16;
#pragma unroll
        for (int jj = 0; jj < 15; jj++) wrow[jj] = sc[jj] * inv;
        wrow[15] = 0.f;
    }
    __syncthreads();

    // cooperative write of zero-padded fp16 A block [128 r][32 jw]
    {
        int r = tid >> 2;                 // 0..127
        int cs = (tid & 3) * 8;
        int il = r >> 3;
        const float* wrow = ws + r * 16;
        unsigned pk[4];
#pragma unroll
        for (int p2 = 0; p2 < 4; p2++) {
            float v0 = 0.f, v1 = 0.f;
            int c0 = cs + p2 * 2, c1 = c0 + 1;
            int j0 = c0 - il, j1 = c1 - il;
            if (j0 >= 0 && j0 < 15) v0 = wrow[j0];
            if (j1 >= 0 && j1 < 15) v1 = wrow[j1];
            __half2 hh = __floats2half2_rn(v0, v1);
            pk[p2] = *reinterpret_cast<unsigned*>(&hh);
        }
        uint4 u; u.x = pk[0]; u.y = pk[1]; u.z = pk[2]; u.w = pk[3];
        *(uint4*)(g_wa + ((size_t)(b * NBLK + blk)) * 4096 + r * 32 + cs) = u;
    }
}

// ---------------------------------------------------------------------------
// ctxmma: context as tensor-core GEMM per 16-i block (unchanged from R12;
// consumes exact hi/lo hs so no new error here)
// ---------------------------------------------------------------------------
#define CTXM_SMEM (65536 + 128 * 80)    // 75776

__global__ __launch_bounds__(256, 2)
void ctxmma(float* __restrict__ out) {
    extern __shared__ char smemraw[];
    uint32_t Bb = smem_u32(smemraw);
    uint32_t Ab = Bb + 65536;
    const int blk = blockIdx.x, b = blockIdx.y;
    const int i0 = blk * 16;
    const int tid = threadIdx.x, wid = tid >> 5, lane = tid & 31;

    {
        const char* a2 = (const char*)g_a2 + (size_t)b * SS * (K2 * 2);
#pragma unroll
        for (int it = 0; it < 16; it++) {
            int idx = tid + it * 256;
            int r = idx >> 6, cu = idx & 63;
            int j = i0 - LR + (r & 31);
            j = j < 0 ? 0 : (j >= SS ? SS - 1 : j);
            const char* src = a2 + (size_t)j * (K2 * 2) + (r >> 5) * 1024 + cu * 16;
            cp16(Bb + r * 1024 + ((cu ^ (r & 7)) << 4), src);
        }
    }
    {
        const char* wa = (const char*)g_wa + (size_t)(b * NBLK + blk) * 8192;
#pragma unroll
        for (int it = 0; it < 2; it++) {
            int idx = tid + it * 256;
            int r = idx >> 2, cu = idx & 3;
            cp16(Ab + r * 80 + cu * 16, wa + r * 64 + cu * 16);
        }
    }
    CP_COMMIT();
    asm volatile("cp.async.wait_group 0;" ::: "memory");
    __syncthreads();

    const int wm = wid & 1, wn = wid >> 1;
    const int er = lane >> 2, ec = (lane & 3) * 2;
    const int arow = wm * 64 + (lane & 15);
    const int acg  = ((lane >> 4) & 1) * 16;

#pragma unroll
    for (int dp = 0; dp < 4; dp++) {
        const int n0 = dp * 128 + wn * 32;
        float acc[4][4][4];
#pragma unroll
        for (int mi = 0; mi < 4; mi++)
#pragma unroll
            for (int ni = 0; ni < 4; ni++)
#pragma unroll
                for (int r = 0; r < 4; r++) acc[mi][ni][r] = 0.f;

#pragma unroll
        for (int ks = 0; ks < 4; ks++) {
            uint32_t af[4][4], bf[4][2];
#pragma unroll
            for (int mi = 0; mi < 4; mi++)
                ldm_x4(af[mi][0], af[mi][1], af[mi][2], af[mi][3],
                       Ab + (arow + mi * 16) * 80 + (ks & 1) * 32 + acg);
#pragma unroll
            for (int ni = 0; ni < 4; ni++) {
                int kr = ks * 16 + (lane & 15);
                int cu = (n0 + ni * 8) >> 3;
                ldm_x2t(bf[ni][0], bf[ni][1],
                        Bb + kr * 1024 + ((cu ^ (kr & 7)) << 4));
            }
#pragma unroll
            for (int mi = 0; mi < 4; mi++)
#pragma unroll
                for (int ni = 0; ni < 4; ni++)
                    mma16816(acc[mi][ni], af[mi], bf[ni]);
        }

#pragma unroll
        for (int mi = 0; mi < 4; mi++) {
            int r0 = wm * 64 + mi * 16 + er;
            int r1 = r0 + 8;
            int il0 = r0 >> 3, h0 = r0 & 7;
            int il1 = r1 >> 3, h1 = r1 & 7;
            float* o0 = out + (((size_t)b * HH + h0) * SS + i0 + il0) * DD;
            float* o1 = out + (((size_t)b * HH + h1) * SS + i0 + il1) * DD;
#pragma unroll
            for (int ni = 0; ni < 4; ni++) {
                int d = n0 + ni * 8 + ec;
                *(float2*)(o0 + d) = make_float2(acc[mi][ni][0], acc[mi][ni][1]);
                *(float2*)(o1 + d) = make_float2(acc[mi][ni][2], acc[mi][ni][3]);
            }
        }
    }
}

// ---------------------------------------------------------------------------
extern "C" void kernel_launch(void* const* d_in, const int* in_sizes, int n_in,
                              void* d_out, int out_size) {
    const float* hs = (const float*)d_in[0];
    const float* Wq = (const float*)d_in[1];
    const float* Wk = (const float*)d_in[2];
    float* out = (float*)d_out;

    cudaFuncSetAttribute(gemm2, cudaFuncAttributeMaxDynamicSharedMemorySize, GEMM_SMEM);
    cudaFuncSetAttribute(wts, cudaFuncAttributeMaxDynamicSharedMemorySize, WTS_SMEM);
    cudaFuncSetAttribute(ctxmma, cudaFuncAttributeMaxDynamicSharedMemorySize, CTXM_SMEM);

    split_hs<<<2048, 256>>>(hs);
    split_w<<<dim3(16, 16, 2), dim3(32, 8)>>>(Wq, Wk);
    gemm2<<<dim3(32, 4, 2), 256, GEMM_SMEM>>>();
    wts<<<dim3(NBLK, BB), 512, WTS_SMEM>>>();
    ctxmma<<<dim3(NBLK, BB), 256, CTXM_SMEM>>>(out);
}

// round 14
// speedup vs baseline: 2.8329x; 1.2683x over previous
#include <cuda_runtime.h>
#include <cuda_fp16.h>
#include <cstdint>

#define BB 2
#define SS 2048
#define DD 512
#define HH 8
#define LR 7
#define MTOT (BB*SS)        // 4096
#define K2 (2*DD)           // 1024
#define NBLK (SS/16)        // 128 i-blocks per batch

// scratch
__device__ __half g_qh[MTOT * DD];       // q projection, fp16
__device__ __half g_kh[MTOT * DD];       // k projection, fp16
__device__ __half g_a2[MTOT * K2];       // hs [hi | lo] along K (ctxf B needs both)
__device__ __half g_b2q[DD * DD];        // Wq^T fp16, rows = n
__device__ __half g_b2k[DD * DD];        // Wk^T fp16, rows = n

#define SWZ128(off) ((off) ^ (((off) >> 3) & 0x70))

__device__ __forceinline__ uint32_t smem_u32(const void* p) {
    uint32_t a;
    asm("{ .reg .u64 t; cvta.to.shared.u64 t, %1; cvt.u32.u64 %0, t; }" : "=r"(a) : "l"(p));
    return a;
}
__device__ __forceinline__ void cp16(uint32_t s, const void* g) {
    asm volatile("cp.async.cg.shared.global [%0], [%1], 16;" :: "r"(s), "l"(g));
}
#define CP_COMMIT() asm volatile("cp.async.commit_group;" ::: "memory")

__device__ __forceinline__ void ldm_x4(uint32_t& r0, uint32_t& r1, uint32_t& r2, uint32_t& r3, uint32_t a) {
    asm volatile("ldmatrix.sync.aligned.m8n8.x4.shared.b16 {%0,%1,%2,%3}, [%4];"
                 : "=r"(r0), "=r"(r1), "=r"(r2), "=r"(r3) : "r"(a));
}
__device__ __forceinline__ void ldm_x2(uint32_t& r0, uint32_t& r1, uint32_t a) {
    asm volatile("ldmatrix.sync.aligned.m8n8.x2.shared.b16 {%0,%1}, [%2];"
                 : "=r"(r0), "=r"(r1) : "r"(a));
}
__device__ __forceinline__ void ldm_x2t(uint32_t& r0, uint32_t& r1, uint32_t a) {
    asm volatile("ldmatrix.sync.aligned.m8n8.x2.trans.shared.b16 {%0,%1}, [%2];"
                 : "=r"(r0), "=r"(r1) : "r"(a));
}
__device__ __forceinline__ void mma16816(float* d, const uint32_t* a, const uint32_t* b) {
    asm volatile("mma.sync.aligned.m16n8k16.row.col.f32.f16.f16.f32 "
                 "{%0,%1,%2,%3}, {%4,%5,%6,%7}, {%8,%9}, {%0,%1,%2,%3};"
                 : "+f"(d[0]), "+f"(d[1]), "+f"(d[2]), "+f"(d[3])
                 : "r"(a[0]), "r"(a[1]), "r"(a[2]), "r"(a[3]), "r"(b[0]), "r"(b[1]));
}
__device__ __forceinline__ void unpack8(uint4 v, float* f) {
    const __half2* hp = (const __half2*)&v;
#pragma unroll
    for (int i = 0; i < 4; i++) {
        float2 x = __half22float2(hp[i]);
        f[2*i] = x.x; f[2*i+1] = x.y;
    }
}

// ---------------------------------------------------------------------------
// split hidden_states into fp16 hi/lo, doubled K layout [hi | lo]
// ---------------------------------------------------------------------------
__global__ void split_hs(const float* __restrict__ hs) {
    int idx = blockIdx.x * 256 + threadIdx.x;
    int m = idx >> 7;
    int c = idx & 127;
    float4 v = ((const float4*)hs)[idx];
    __half hx = __float2half(v.x), hy = __float2half(v.y);
    __half hz = __float2half(v.z), hw = __float2half(v.w);
    __half lx = __float2half(v.x - __half2float(hx));
    __half ly = __float2half(v.y - __half2float(hy));
    __half lz = __float2half(v.z - __half2float(hz));
    __half lw = __float2half(v.w - __half2float(hw));
    __half2 H0; H0.x = hx; H0.y = hy;
    __half2 H1; H1.x = hz; H1.y = hw;
    __half2 L0; L0.x = lx; L0.y = ly;
    __half2 L1; L1.x = lz; L1.y = lw;
    __half* p = g_a2 + (size_t)m * K2 + 4 * c;
    *(__half2*)(p)        = H0; *(__half2*)(p + 2)        = H1;
    *(__half2*)(p + DD)   = L0; *(__half2*)(p + DD + 2)   = L1;
}

// ---------------------------------------------------------------------------
// split + transpose W (stored [k, n]) into fp16 [n, 512]
// ---------------------------------------------------------------------------
__global__ void split_w(const float* __restrict__ Wq, const float* __restrict__ Wk) {
    __shared__ float t[32][33];
    const float* W = blockIdx.z ? Wk : Wq;
    __half* B2 = blockIdx.z ? g_b2k : g_b2q;
    int n0 = blockIdx.x * 32, k0 = blockIdx.y * 32;
    int tx = threadIdx.x, ty = threadIdx.y;
#pragma unroll
    for (int r = 0; r < 4; r++)
        t[ty + r * 8][tx] = W[(size_t)(k0 + ty + r * 8) * DD + n0 + tx];
    __syncthreads();
#pragma unroll
    for (int r = 0; r < 4; r++) {
        int n = n0 + ty + r * 8, k = k0 + tx;
        B2[(size_t)n * DD + k] = __float2half(t[tx][ty + r * 8]);
    }
}

// ---------------------------------------------------------------------------
// mma.sync fp16 GEMM: q and k projections, both K=512 (hs_hi x W_hi), fp16 out
// CTA tile 128x128, 8 warps of 64x32, K-tile 64, 3-stage cp.async pipeline
// ---------------------------------------------------------------------------
#define MT 128
#define NT 128
#define NKT 8          // 512/64
#define STG 32768u
#define NSTG 3
#define GEMM_SMEM (NSTG * STG)

__device__ __forceinline__ void load_tile(int tile, int stg,
                                          const char* Ab, const char* Bb,
                                          uint32_t sb, int tid) {
    size_t koff = (size_t)tile * 128;    // 64 halfs = 128 bytes
    uint32_t sA = sb + (uint32_t)stg * STG;
    uint32_t sB = sA + 16384u;
#pragma unroll
    for (int c = 0; c < 4; c++) {
        int q = tid + c * 256;
        int r = q >> 3, col = (q & 7) * 16;
        cp16(sA + SWZ128(r * 128 + col), Ab + (size_t)r * 2048 + koff + col);   // hi half of g_a2 row
    }
#pragma unroll
    for (int c = 0; c < 4; c++) {
        int q = tid + c * 256;
        int r = q >> 3, col = (q & 7) * 16;
        cp16(sB + SWZ128(r * 128 + col), Bb + (size_t)r * 1024 + koff + col);
    }
}

__global__ __launch_bounds__(256, 2)
void gemm2() {
    extern __shared__ char smem[];
    uint32_t sb = smem_u32(smem);
    const int tid = threadIdx.x, wid = tid >> 5, lane = tid & 31;
    const int m0 = blockIdx.x * MT;
    const int n0 = blockIdx.y * NT;

    const __half* B2 = blockIdx.z ? g_b2k : g_b2q;
    __half* C       = blockIdx.z ? g_kh : g_qh;

    const char* Ab = (const char*)g_a2 + (size_t)m0 * 2048;
    const char* Bb = (const char*)B2 + (size_t)n0 * 1024;

    const int wm = wid & 1;
    const int wn = wid >> 1;

    float acc[4][4][4];
#pragma unroll
    for (int i = 0; i < 4; i++)
#pragma unroll
        for (int j = 0; j < 4; j++)
#pragma unroll
            for (int r = 0; r < 4; r++) acc[i][j][r] = 0.f;

    load_tile(0, 0, Ab, Bb, sb, tid); CP_COMMIT();
    load_tile(1, 1, Ab, Bb, sb, tid); CP_COMMIT();

    const int a_row = wm * 64 + (lane & 15);
    const int a_cg  = (lane >> 4) * 16;
    const int b_row = wn * 32 + (lane & 7);
    const int b_cg  = ((lane >> 3) & 1) * 16;

    for (int t = 0; t < NKT; t++) {
        asm volatile("cp.async.wait_group 1;" ::: "memory");
        __syncthreads();

        if (t + 2 < NKT)
            load_tile(t + 2, (t + 2) % NSTG, Ab, Bb, sb, tid);
        CP_COMMIT();

        uint32_t sA = sb + (uint32_t)(t % NSTG) * STG;
        uint32_t sB = sA + 16384u;
#pragma unroll
        for (int ks = 0; ks < 4; ks++) {
            uint32_t af[4][4], bf[4][2];
#pragma unroll
            for (int mi = 0; mi < 4; mi++)
                ldm_x4(af[mi][0], af[mi][1], af[mi][2], af[mi][3],
                       sA + SWZ128((a_row + mi * 16) * 128 + ks * 32 + a_cg));
#pragma unroll
            for (int ni = 0; ni < 4; ni++)
                ldm_x2(bf[ni][0], bf[ni][1],
                       sB + SWZ128((b_row + ni * 8) * 128 + ks * 32 + b_cg));
#pragma unroll
            for (int mi = 0; mi < 4; mi++)
#pragma unroll
                for (int ni = 0; ni < 4; ni++)
                    mma16816(acc[mi][ni], af[mi], bf[ni]);
        }
    }

    const int er = lane >> 2;
    const int ec = (lane & 3) * 2;
#pragma unroll
    for (int mi = 0; mi < 4; mi++) {
        int r0 = m0 + wm * 64 + mi * 16 + er;
#pragma unroll
        for (int ni = 0; ni < 4; ni++) {
            int cc = n0 + wn * 32 + ni * 8 + ec;
            __half2 v01 = __floats2half2_rn(acc[mi][ni][0], acc[mi][ni][1]);
            __half2 v23 = __floats2half2_rn(acc[mi][ni][2], acc[mi][ni][3]);
            *(__half2*)(C + (size_t)r0 * DD + cc) = v01;
            *(__half2*)(C + (size_t)(r0 + 8) * DD + cc) = v23;
        }
    }
}

// ---------------------------------------------------------------------------
// ctxf: fused band-softmax weights + context MMA per 16-i block.
// Phase 1: k window (30 rows fp16) in smem (B region), warp computes weights
//          for 2 i values -> ws[128][16].
// Phase 2: issue B hs-window cp.async, build fp16 A block in smem from ws,
//          then MMA + scatter epilogue (proven ctxmma body).
// smem: B 64KB | A 10KB | ws 8KB = 82KB -> 2 CTAs/SM. grid (128, 2).
// ---------------------------------------------------------------------------
#define CTXF_SMEM (65536 + 128 * 80 + 128 * 16 * 4)   // 83968

__global__ __launch_bounds__(256, 2)
void ctxf(float* __restrict__ out) {
    extern __shared__ char smemraw[];
    uint32_t Bb = smem_u32(smemraw);
    uint32_t Ab = Bb + 65536;
    char* Abp = smemraw + 65536;
    float* ws = (float*)(smemraw + 65536 + 10240);    // [128][16]
    uint4* kw = (uint4*)smemraw;                      // phase 1: [30][64] units

    const int blk = blockIdx.x, b = blockIdx.y;
    const int i0 = blk * 16;
    const int tid = threadIdx.x, wid = tid >> 5, lane = tid & 31;

    // ---- phase 1a: stage k window (swizzled) ----
    for (int idx = tid; idx < 30 * 64; idx += 256) {
        int r = idx >> 6, u = idx & 63;
        int us = u ^ ((u >> 3) & 7);
        int j = i0 - LR + r;
        j = j < 0 ? 0 : (j >= SS ? SS - 1 : j);
        kw[r * 64 + us] = ((const uint4*)(g_kh + ((size_t)b * SS + j) * DD))[u];
    }
    __syncthreads();

    // ---- phase 1b: weights, warp handles il = wid and wid+8 ----
    const int h = lane >> 2, g = lane & 3;
    const int u0 = 8 * h + 2 * g;
    const int us0 = u0 ^ h;
    const int us1 = (u0 + 1) ^ h;
#pragma unroll
    for (int half = 0; half < 2; half++) {
        const int il = wid + half * 8;
        const int i = i0 + il;
        const __half* qrow = g_qh + ((size_t)b * SS + i) * DD + h * 64 + g * 16;
        float qf[16];
        unpack8(*(const uint4*)qrow, qf);
        unpack8(*(const uint4*)(qrow + 8), qf + 8);

        float sc[15];
#pragma unroll
        for (int jj = 0; jj < 15; jj++) {
            int j = i - LR + jj;
            bool valid = (j >= 0) && (j < SS);
            const uint4* kr = kw + (il + jj) * 64;
            float kf[16];
            unpack8(kr[us0], kf);
            unpack8(kr[us1], kf + 8);
            float p = 0.f;
#pragma unroll
            for (int t = 0; t < 16; t++) p += qf[t] * kf[t];
            p += __shfl_xor_sync(0xffffffffu, p, 1);
            p += __shfl_xor_sync(0xffffffffu, p, 2);
            sc[jj] = valid ? p * 0.125f : -1e30f;
        }
        float m = -1e30f;
#pragma unroll
        for (int jj = 0; jj < 15; jj++) m = fmaxf(m, sc[jj]);
        float s = 0.f;
#pragma unroll
        for (int jj = 0; jj < 15; jj++) { sc[jj] = __expf(sc[jj] - m); s += sc[jj]; }
        float inv = 1.f / s;
        if (g == 0) {
            float* wrow = ws + (il * 8 + h) * 16;
#pragma unroll
            for (int jj = 0; jj < 15; jj++) wrow[jj] = sc[jj] * inv;
            wrow[15] = 0.f;
        }
    }
    __syncthreads();   // weights done; k window free for reuse

    // ---- phase 2a: issue B staging (hs hi/lo window, overwrites k region) ----
    {
        const char* a2 = (const char*)g_a2 + (size_t)b * SS * (K2 * 2);
#pragma unroll
        for (int it = 0; it < 16; it++) {
            int idx = tid + it * 256;
            int r = idx >> 6, cu = idx & 63;
            int j = i0 - LR + (r & 31);
            j = j < 0 ? 0 : (j >= SS ? SS - 1 : j);
            const char* src = a2 + (size_t)j * (K2 * 2) + (r >> 5) * 1024 + cu * 16;
            cp16(Bb + r * 1024 + ((cu ^ (r & 7)) << 4), src);
        }
        CP_COMMIT();
    }

    // ---- phase 2b: build fp16 zero-padded A block [128 r][32 jw] in smem ----
    {
        int r = tid >> 1;                 // 0..127
        int il = r >> 3;
        const float* wrow = ws + r * 16;
#pragma unroll
        for (int q8 = 0; q8 < 2; q8++) {
            int base = (tid & 1) * 16 + q8 * 8;   // col start 0,8,16,24
            unsigned pk[4];
#pragma unroll
            for (int p2 = 0; p2 < 4; p2++) {
                int c0 = base + p2 * 2, c1 = c0 + 1;
                float v0 = 0.f, v1 = 0.f;
                int j0 = c0 - il, j1 = c1 - il;
                if (j0 >= 0 && j0 < 15) v0 = wrow[j0];
                if (j1 >= 0 && j1 < 15) v1 = wrow[j1];
                __half2 hh = __floats2half2_rn(v0, v1);
                pk[p2] = *reinterpret_cast<unsigned*>(&hh);
            }
            uint4 u4; u4.x = pk[0]; u4.y = pk[1]; u4.z = pk[2]; u4.w = pk[3];
            *(uint4*)(Abp + r * 80 + base * 2) = u4;
        }
    }
    asm volatile("cp.async.wait_group 0;" ::: "memory");
    __syncthreads();

    // ---- phase 3: MMA + scatter epilogue ----
    const int wm = wid & 1, wn = wid >> 1;
    const int er = lane >> 2, ec = (lane & 3) * 2;
    const int arow = wm * 64 + (lane & 15);
    const int acg  = ((lane >> 4) & 1) * 16;

#pragma unroll
    for (int dp = 0; dp < 4; dp++) {
        const int n0 = dp * 128 + wn * 32;
        float acc[4][4][4];
#pragma unroll
        for (int mi = 0; mi < 4; mi++)
#pragma unroll
            for (int ni = 0; ni < 4; ni++)
#pragma unroll
                for (int r = 0; r < 4; r++) acc[mi][ni][r] = 0.f;

#pragma unroll
        for (int ks = 0; ks < 4; ks++) {
            uint32_t af[4][4], bf[4][2];
#pragma unroll
            for (int mi = 0; mi < 4; mi++)
                ldm_x4(af[mi][0], af[mi][1], af[mi][2], af[mi][3],
                       Ab + (arow + mi * 16) * 80 + (ks & 1) * 32 + acg);
#pragma unroll
            for (int ni = 0; ni < 4; ni++) {
                int kr = ks * 16 + (lane & 15);
                int cu = (n0 + ni * 8) >> 3;
                ldm_x2t(bf[ni][0], bf[ni][1],
                        Bb + kr * 1024 + ((cu ^ (kr & 7)) << 4));
            }
#pragma unroll
            for (int mi = 0; mi < 4; mi++)
#pragma unroll
                for (int ni = 0; ni < 4; ni++)
                    mma16816(acc[mi][ni], af[mi], bf[ni]);
        }

#pragma unroll
        for (int mi = 0; mi < 4; mi++) {
            int r0 = wm * 64 + mi * 16 + er;
            int r1 = r0 + 8;
            int il0 = r0 >> 3, h0 = r0 & 7;
            int il1 = r1 >> 3, h1 = r1 & 7;
            float* o0 = out + (((size_t)b * HH + h0) * SS + i0 + il0) * DD;
            float* o1 = out + (((size_t)b * HH + h1) * SS + i0 + il1) * DD;
#pragma unroll
            for (int ni = 0; ni < 4; ni++) {
                int d = n0 + ni * 8 + ec;
                *(float2*)(o0 + d) = make_float2(acc[mi][ni][0], acc[mi][ni][1]);
                *(float2*)(o1 + d) = make_float2(acc[mi][ni][2], acc[mi][ni][3]);
            }
        }
    }
}

// ---------------------------------------------------------------------------
extern "C" void kernel_launch(void* const* d_in, const int* in_sizes, int n_in,
                              void* d_out, int out_size) {
    const float* hs = (const float*)d_in[0];
    const float* Wq = (const float*)d_in[1];
    const float* Wk = (const float*)d_in[2];
    float* out = (float*)d_out;

    cudaFuncSetAttribute(gemm2, cudaFuncAttributeMaxDynamicSharedMemorySize, GEMM_SMEM);
    cudaFuncSetAttribute(ctxf, cudaFuncAttributeMaxDynamicSharedMemorySize, CTXF_SMEM);

    split_hs<<<2048, 256>>>(hs);
    split_w<<<dim3(16, 16, 2), dim3(32, 8)>>>(Wq, Wk);
    gemm2<<<dim3(32, 4, 2), 256, GEMM_SMEM>>>();
    ctxf<<<dim3(NBLK, BB), 256, CTXF_SMEM>>>(out);
}

// round 15
// speedup vs baseline: 2.9948x; 1.0572x over previous
#include <cuda_runtime.h>
#include <cuda_fp16.h>
#include <cstdint>

#define BB 2
#define SS 2048
#define DD 512
#define HH 8
#define LR 7
#define MTOT (BB*SS)        // 4096
#define NBLK (SS/16)        // 128 i-blocks per batch

// scratch
__device__ __half g_qh[MTOT * DD];       // q projection, fp16
__device__ __half g_kh[MTOT * DD];       // k projection, fp16
__device__ __half g_ah[MTOT * DD];       // hs fp16 (hi only)
__device__ __half g_b2q[DD * DD];        // Wq^T fp16, rows = n
__device__ __half g_b2k[DD * DD];        // Wk^T fp16, rows = n

#define SWZ128(off) ((off) ^ (((off) >> 3) & 0x70))

__device__ __forceinline__ uint32_t smem_u32(const void* p) {
    uint32_t a;
    asm("{ .reg .u64 t; cvta.to.shared.u64 t, %1; cvt.u32.u64 %0, t; }" : "=r"(a) : "l"(p));
    return a;
}
__device__ __forceinline__ void cp16(uint32_t s, const void* g) {
    asm volatile("cp.async.cg.shared.global [%0], [%1], 16;" :: "r"(s), "l"(g));
}
#define CP_COMMIT() asm volatile("cp.async.commit_group;" ::: "memory")

__device__ __forceinline__ void ldm_x4(uint32_t& r0, uint32_t& r1, uint32_t& r2, uint32_t& r3, uint32_t a) {
    asm volatile("ldmatrix.sync.aligned.m8n8.x4.shared.b16 {%0,%1,%2,%3}, [%4];"
                 : "=r"(r0), "=r"(r1), "=r"(r2), "=r"(r3) : "r"(a));
}
__device__ __forceinline__ void ldm_x2(uint32_t& r0, uint32_t& r1, uint32_t a) {
    asm volatile("ldmatrix.sync.aligned.m8n8.x2.shared.b16 {%0,%1}, [%2];"
                 : "=r"(r0), "=r"(r1) : "r"(a));
}
__device__ __forceinline__ void ldm_x2t(uint32_t& r0, uint32_t& r1, uint32_t a) {
    asm volatile("ldmatrix.sync.aligned.m8n8.x2.trans.shared.b16 {%0,%1}, [%2];"
                 : "=r"(r0), "=r"(r1) : "r"(a));
}
__device__ __forceinline__ void mma16816(float* d, const uint32_t* a, const uint32_t* b) {
    asm volatile("mma.sync.aligned.m16n8k16.row.col.f32.f16.f16.f32 "
                 "{%0,%1,%2,%3}, {%4,%5,%6,%7}, {%8,%9}, {%0,%1,%2,%3};"
                 : "+f"(d[0]), "+f"(d[1]), "+f"(d[2]), "+f"(d[3])
                 : "r"(a[0]), "r"(a[1]), "r"(a[2]), "r"(a[3]), "r"(b[0]), "r"(b[1]));
}
__device__ __forceinline__ void unpack8(uint4 v, float* f) {
    const __half2* hp = (const __half2*)&v;
#pragma unroll
    for (int i = 0; i < 4; i++) {
        float2 x = __half22float2(hp[i]);
        f[2*i] = x.x; f[2*i+1] = x.y;
    }
}

// ---------------------------------------------------------------------------
// split hidden_states to fp16 (hi only)
// ---------------------------------------------------------------------------
__global__ void split_hs(const float* __restrict__ hs) {
    int idx = blockIdx.x * 256 + threadIdx.x;     // float4 index
    float4 v = ((const float4*)hs)[idx];
    __half2 h0 = __floats2half2_rn(v.x, v.y);
    __half2 h1 = __floats2half2_rn(v.z, v.w);
    __half2* p = (__half2*)(g_ah + 4 * (size_t)idx);
    p[0] = h0; p[1] = h1;
}

// ---------------------------------------------------------------------------
// split + transpose W (stored [k, n]) into fp16 [n, 512]
// ---------------------------------------------------------------------------
__global__ void split_w(const float* __restrict__ Wq, const float* __restrict__ Wk) {
    __shared__ float t[32][33];
    const float* W = blockIdx.z ? Wk : Wq;
    __half* B2 = blockIdx.z ? g_b2k : g_b2q;
    int n0 = blockIdx.x * 32, k0 = blockIdx.y * 32;
    int tx = threadIdx.x, ty = threadIdx.y;
#pragma unroll
    for (int r = 0; r < 4; r++)
        t[ty + r * 8][tx] = W[(size_t)(k0 + ty + r * 8) * DD + n0 + tx];
    __syncthreads();
#pragma unroll
    for (int r = 0; r < 4; r++) {
        int n = n0 + ty + r * 8, k = k0 + tx;
        B2[(size_t)n * DD + k] = __float2half(t[tx][ty + r * 8]);
    }
}

// ---------------------------------------------------------------------------
// mma.sync fp16 GEMM: q and k projections, K=512, fp16 out
// ---------------------------------------------------------------------------
#define MT 128
#define NT 128
#define NKT 8          // 512/64
#define STG 32768u
#define NSTG 3
#define GEMM_SMEM (NSTG * STG)

__device__ __forceinline__ void load_tile(int tile, int stg,
                                          const char* Ab, const char* Bb,
                                          uint32_t sb, int tid) {
    size_t koff = (size_t)tile * 128;
    uint32_t sA = sb + (uint32_t)stg * STG;
    uint32_t sB = sA + 16384u;
#pragma unroll
    for (int c = 0; c < 4; c++) {
        int q = tid + c * 256;
        int r = q >> 3, col = (q & 7) * 16;
        cp16(sA + SWZ128(r * 128 + col), Ab + (size_t)r * 1024 + koff + col);
    }
#pragma unroll
    for (int c = 0; c < 4; c++) {
        int q = tid + c * 256;
        int r = q >> 3, col = (q & 7) * 16;
        cp16(sB + SWZ128(r * 128 + col), Bb + (size_t)r * 1024 + koff + col);
    }
}

__global__ __launch_bounds__(256, 2)
void gemm2() {
    extern __shared__ char smem[];
    uint32_t sb = smem_u32(smem);
    const int tid = threadIdx.x, wid = tid >> 5, lane = tid & 31;
    const int m0 = blockIdx.x * MT;
    const int n0 = blockIdx.y * NT;

    const __half* B2 = blockIdx.z ? g_b2k : g_b2q;
    __half* C       = blockIdx.z ? g_kh : g_qh;

    const char* Ab = (const char*)g_ah + (size_t)m0 * 1024;
    const char* Bb = (const char*)B2 + (size_t)n0 * 1024;

    const int wm = wid & 1;
    const int wn = wid >> 1;

    float acc[4][4][4];
#pragma unroll
    for (int i = 0; i < 4; i++)
#pragma unroll
        for (int j = 0; j < 4; j++)
#pragma unroll
            for (int r = 0; r < 4; r++) acc[i][j][r] = 0.f;

    load_tile(0, 0, Ab, Bb, sb, tid); CP_COMMIT();
    load_tile(1, 1, Ab, Bb, sb, tid); CP_COMMIT();

    const int a_row = wm * 64 + (lane & 15);
    const int a_cg  = (lane >> 4) * 16;
    const int b_row = wn * 32 + (lane & 7);
    const int b_cg  = ((lane >> 3) & 1) * 16;

    for (int t = 0; t < NKT; t++) {
        asm volatile("cp.async.wait_group 1;" ::: "memory");
        __syncthreads();

        if (t + 2 < NKT)
            load_tile(t + 2, (t + 2) % NSTG, Ab, Bb, sb, tid);
        CP_COMMIT();

        uint32_t sA = sb + (uint32_t)(t % NSTG) * STG;
        uint32_t sB = sA + 16384u;
#pragma unroll
        for (int ks = 0; ks < 4; ks++) {
            uint32_t af[4][4], bf[4][2];
#pragma unroll
            for (int mi = 0; mi < 4; mi++)
                ldm_x4(af[mi][0], af[mi][1], af[mi][2], af[mi][3],
                       sA + SWZ128((a_row + mi * 16) * 128 + ks * 32 + a_cg));
#pragma unroll
            for (int ni = 0; ni < 4; ni++)
                ldm_x2(bf[ni][0], bf[ni][1],
                       sB + SWZ128((b_row + ni * 8) * 128 + ks * 32 + b_cg));
#pragma unroll
            for (int mi = 0; mi < 4; mi++)
#pragma unroll
                for (int ni = 0; ni < 4; ni++)
                    mma16816(acc[mi][ni], af[mi], bf[ni]);
        }
    }

    const int er = lane >> 2;
    const int ec = (lane & 3) * 2;
#pragma unroll
    for (int mi = 0; mi < 4; mi++) {
        int r0 = m0 + wm * 64 + mi * 16 + er;
#pragma unroll
        for (int ni = 0; ni < 4; ni++) {
            int cc = n0 + wn * 32 + ni * 8 + ec;
            __half2 v01 = __floats2half2_rn(acc[mi][ni][0], acc[mi][ni][1]);
            __half2 v23 = __floats2half2_rn(acc[mi][ni][2], acc[mi][ni][3]);
            *(__half2*)(C + (size_t)r0 * DD + cc) = v01;
            *(__half2*)(C + (size_t)(r0 + 8) * DD + cc) = v23;
        }
    }
}

// ---------------------------------------------------------------------------
// ctxf v2: fused band softmax + context MMA per 16-i block, K=32 (hi only).
// kw and B in SEPARATE smem regions; both cp.async groups issued up front so
// the B load hides under softmax compute.
// smem: B 32KB | A 10KB | ws 8KB | kw 30KB = 80KB -> 2 CTAs/SM. grid (128, 2).
// ---------------------------------------------------------------------------
#define CTXF_SMEM (32768 + 10240 + 8192 + 30720)   // 81920

__global__ __launch_bounds__(256, 2)
void ctxf(float* __restrict__ out) {
    extern __shared__ char smemraw[];
    uint32_t Bb = smem_u32(smemraw);                   // B: 32 rows x 1KB
    uint32_t Ab = Bb + 32768;                          // A: 128 rows x 80B
    char* Abp = smemraw + 32768;
    float* ws = (float*)(smemraw + 32768 + 10240);     // [128][16]
    uint4* kw = (uint4*)(smemraw + 32768 + 10240 + 8192);  // [30][64] units

    const int blk = blockIdx.x, b = blockIdx.y;
    const int i0 = blk * 16;
    const int tid = threadIdx.x, wid = tid >> 5, lane = tid & 31;

    // ---- issue k-window staging (group 0) ----
    uint32_t kwb = smem_u32(kw);
    for (int idx = tid; idx < 30 * 64; idx += 256) {
        int r = idx >> 6, u = idx & 63;
        int us = u ^ ((u >> 3) & 7);
        int j = i0 - LR + r;
        j = j < 0 ? 0 : (j >= SS ? SS - 1 : j);
        cp16(kwb + (r * 64 + us) * 16,
             (const char*)(g_kh + ((size_t)b * SS + j) * DD) + u * 16);
    }
    CP_COMMIT();

    // ---- issue B staging (group 1): 32 hs rows, j = i0-7+r ----
    {
        const char* ah = (const char*)g_ah + (size_t)b * SS * 1024;
#pragma unroll
        for (int it = 0; it < 8; it++) {
            int idx = tid + it * 256;
            int r = idx >> 6, cu = idx & 63;
            int j = i0 - LR + r;
            j = j < 0 ? 0 : (j >= SS ? SS - 1 : j);
            cp16(Bb + r * 1024 + ((cu ^ (r & 7)) << 4),
                 ah + (size_t)j * 1024 + cu * 16);
        }
        CP_COMMIT();
    }

    asm volatile("cp.async.wait_group 1;" ::: "memory");   // kw ready
    __syncthreads();

    // ---- band softmax: warp handles il = wid and wid+8 ----
    const int h = lane >> 2, g = lane & 3;
    const int u0 = 8 * h + 2 * g;
    const int us0 = u0 ^ h;
    const int us1 = (u0 + 1) ^ h;
#pragma unroll
    for (int half = 0; half < 2; half++) {
        const int il = wid + half * 8;
        const int i = i0 + il;
        const __half* qrow = g_qh + ((size_t)b * SS + i) * DD + h * 64 + g * 16;
        float qf[16];
        unpack8(*(const uint4*)qrow, qf);
        unpack8(*(const uint4*)(qrow + 8), qf + 8);

        float sc[15];
#pragma unroll
        for (int jj = 0; jj < 15; jj++) {
            int j = i - LR + jj;
            bool valid = (j >= 0) && (j < SS);
            const uint4* kr = kw + (il + jj) * 64;
            float kf[16];
            unpack8(kr[us0], kf);
            unpack8(kr[us1], kf + 8);
            float p = 0.f;
#pragma unroll
            for (int t = 0; t < 16; t++) p += qf[t] * kf[t];
            p += __shfl_xor_sync(0xffffffffu, p, 1);
            p += __shfl_xor_sync(0xffffffffu, p, 2);
            sc[jj] = valid ? p * 0.125f : -1e30f;
        }
        float m = -1e30f;
#pragma unroll
        for (int jj = 0; jj < 15; jj++) m = fmaxf(m, sc[jj]);
        float s = 0.f;
#pragma unroll
        for (int jj = 0; jj < 15; jj++) { sc[jj] = __expf(sc[jj] - m); s += sc[jj]; }
        float inv = 1.f / s;
        if (g == 0) {
            float* wrow = ws + (il * 8 + h) * 16;
#pragma unroll
            for (int jj = 0; jj < 15; jj++) wrow[jj] = sc[jj] * inv;
            wrow[15] = 0.f;
        }
    }
    __syncthreads();

    // ---- build fp16 zero-padded A block [128 r][32 jw] in smem ----
    {
        int r = tid >> 1;
        int il = r >> 3;
        const float* wrow = ws + r * 16;
#pragma unroll
        for (int q8 = 0; q8 < 2; q8++) {
            int base = (tid & 1) * 16 + q8 * 8;
            unsigned pk[4];
#pragma unroll
            for (int p2 = 0; p2 < 4; p2++) {
                int c0 = base + p2 * 2, c1 = c0 + 1;
                float v0 = 0.f, v1 = 0.f;
                int j0 = c0 - il, j1 = c1 - il;
                if (j0 >= 0 && j0 < 15) v0 = wrow[j0];
                if (j1 >= 0 && j1 < 15) v1 = wrow[j1];
                __half2 hh = __floats2half2_rn(v0, v1);
                pk[p2] = *reinterpret_cast<unsigned*>(&hh);
            }
            uint4 u4; u4.x = pk[0]; u4.y = pk[1]; u4.z = pk[2]; u4.w = pk[3];
            *(uint4*)(Abp + r * 80 + base * 2) = u4;
        }
    }
    asm volatile("cp.async.wait_group 0;" ::: "memory");   // B ready
    __syncthreads();

    // ---- MMA (K=32, 2 ks steps) + scatter epilogue ----
    const int wm = wid & 1, wn = wid >> 1;
    const int er = lane >> 2, ec = (lane & 3) * 2;
    const int arow = wm * 64 + (lane & 15);
    const int acg  = ((lane >> 4) & 1) * 16;

#pragma unroll
    for (int dp = 0; dp < 4; dp++) {
        const int n0 = dp * 128 + wn * 32;
        float acc[4][4][4];
#pragma unroll
        for (int mi = 0; mi < 4; mi++)
#pragma unroll
            for (int ni = 0; ni < 4; ni++)
#pragma unroll
                for (int r = 0; r < 4; r++) acc[mi][ni][r] = 0.f;

#pragma unroll
        for (int ks = 0; ks < 2; ks++) {
            uint32_t af[4][4], bf[4][2];
#pragma unroll
            for (int mi = 0; mi < 4; mi++)
                ldm_x4(af[mi][0], af[mi][1], af[mi][2], af[mi][3],
                       Ab + (arow + mi * 16) * 80 + ks * 32 + acg);
#pragma unroll
            for (int ni = 0; ni < 4; ni++) {
                int kr = ks * 16 + (lane & 15);
                int cu = (n0 + ni * 8) >> 3;
                ldm_x2t(bf[ni][0], bf[ni][1],
                        Bb + kr * 1024 + ((cu ^ (kr & 7)) << 4));
            }
#pragma unroll
            for (int mi = 0; mi < 4; mi++)
#pragma unroll
                for (int ni = 0; ni < 4; ni++)
                    mma16816(acc[mi][ni], af[mi], bf[ni]);
        }

#pragma unroll
        for (int mi = 0; mi < 4; mi++) {
            int r0 = wm * 64 + mi * 16 + er;
            int r1 = r0 + 8;
            int il0 = r0 >> 3, h0 = r0 & 7;
            int il1 = r1 >> 3, h1 = r1 & 7;
            float* o0 = out + (((size_t)b * HH + h0) * SS + i0 + il0) * DD;
            float* o1 = out + (((size_t)b * HH + h1) * SS + i0 + il1) * DD;
#pragma unroll
            for (int ni = 0; ni < 4; ni++) {
                int d = n0 + ni * 8 + ec;
                *(float2*)(o0 + d) = make_float2(acc[mi][ni][0], acc[mi][ni][1]);
                *(float2*)(o1 + d) = make_float2(acc[mi][ni][2], acc[mi][ni][3]);
            }
        }
    }
}

// ---------------------------------------------------------------------------
extern "C" void kernel_launch(void* const* d_in, const int* in_sizes, int n_in,
                              void* d_out, int out_size) {
    const float* hs = (const float*)d_in[0];
    const float* Wq = (const float*)d_in[1];
    const float* Wk = (const float*)d_in[2];
    float* out = (float*)d_out;

    cudaFuncSetAttribute(gemm2, cudaFuncAttributeMaxDynamicSharedMemorySize, GEMM_SMEM);
    cudaFuncSetAttribute(ctxf, cudaFuncAttributeMaxDynamicSharedMemorySize, CTXF_SMEM);

    split_hs<<<2048, 256>>>(hs);
    split_w<<<dim3(16, 16, 2), dim3(32, 8)>>>(Wq, Wk);
    gemm2<<<dim3(32, 4, 2), 256, GEMM_SMEM>>>();
    ctxf<<<dim3(NBLK, BB), 256, CTXF_SMEM>>>(out);
}

// round 16
// speedup vs baseline: 3.1007x; 1.0354x over previous
#include <cuda_runtime.h>
#include <cuda_fp16.h>
#include <cstdint>

#define BB 2
#define SS 2048
#define DD 512
#define HH 8
#define LR 7
#define MTOT (BB*SS)        // 4096
#define NBLK (SS/16)        // 128 i-blocks per batch

// scratch
__device__ __half g_qh[MTOT * DD];       // q projection, fp16
__device__ __half g_kh[MTOT * DD];       // k projection, fp16
__device__ __half g_ah[MTOT * DD];       // hs fp16
__device__ __half g_b2q[DD * DD];        // Wq^T fp16, rows = n
__device__ __half g_b2k[DD * DD];        // Wk^T fp16, rows = n

#define SWZ128(off) ((off) ^ (((off) >> 3) & 0x70))

__device__ __forceinline__ uint32_t smem_u32(const void* p) {
    uint32_t a;
    asm("{ .reg .u64 t; cvta.to.shared.u64 t, %1; cvt.u32.u64 %0, t; }" : "=r"(a) : "l"(p));
    return a;
}
__device__ __forceinline__ void cp16(uint32_t s, const void* g) {
    asm volatile("cp.async.cg.shared.global [%0], [%1], 16;" :: "r"(s), "l"(g));
}
#define CP_COMMIT() asm volatile("cp.async.commit_group;" ::: "memory")

__device__ __forceinline__ void ldm_x4(uint32_t& r0, uint32_t& r1, uint32_t& r2, uint32_t& r3, uint32_t a) {
    asm volatile("ldmatrix.sync.aligned.m8n8.x4.shared.b16 {%0,%1,%2,%3}, [%4];"
                 : "=r"(r0), "=r"(r1), "=r"(r2), "=r"(r3) : "r"(a));
}
__device__ __forceinline__ void ldm_x2(uint32_t& r0, uint32_t& r1, uint32_t a) {
    asm volatile("ldmatrix.sync.aligned.m8n8.x2.shared.b16 {%0,%1}, [%2];"
                 : "=r"(r0), "=r"(r1) : "r"(a));
}
__device__ __forceinline__ void ldm_x2t(uint32_t& r0, uint32_t& r1, uint32_t a) {
    asm volatile("ldmatrix.sync.aligned.m8n8.x2.trans.shared.b16 {%0,%1}, [%2];"
                 : "=r"(r0), "=r"(r1) : "r"(a));
}
__device__ __forceinline__ void mma16816(float* d, const uint32_t* a, const uint32_t* b) {
    asm volatile("mma.sync.aligned.m16n8k16.row.col.f32.f16.f16.f32 "
                 "{%0,%1,%2,%3}, {%4,%5,%6,%7}, {%8,%9}, {%0,%1,%2,%3};"
                 : "+f"(d[0]), "+f"(d[1]), "+f"(d[2]), "+f"(d[3])
                 : "r"(a[0]), "r"(a[1]), "r"(a[2]), "r"(a[3]), "r"(b[0]), "r"(b[1]));
}
__device__ __forceinline__ uint32_t packh2(float x, float y) {
    __half2 h = __floats2half2_rn(x, y);
    return *reinterpret_cast<uint32_t*>(&h);
}

// ---------------------------------------------------------------------------
// split hidden_states to fp16
// ---------------------------------------------------------------------------
__global__ void split_hs(const float* __restrict__ hs) {
    int idx = blockIdx.x * 256 + threadIdx.x;
    float4 v = ((const float4*)hs)[idx];
    __half2 h0 = __floats2half2_rn(v.x, v.y);
    __half2 h1 = __floats2half2_rn(v.z, v.w);
    __half2* p = (__half2*)(g_ah + 4 * (size_t)idx);
    p[0] = h0; p[1] = h1;
}

// ---------------------------------------------------------------------------
// split + transpose W (stored [k, n]) into fp16 [n, 512]
// ---------------------------------------------------------------------------
__global__ void split_w(const float* __restrict__ Wq, const float* __restrict__ Wk) {
    __shared__ float t[32][33];
    const float* W = blockIdx.z ? Wk : Wq;
    __half* B2 = blockIdx.z ? g_b2k : g_b2q;
    int n0 = blockIdx.x * 32, k0 = blockIdx.y * 32;
    int tx = threadIdx.x, ty = threadIdx.y;
#pragma unroll
    for (int r = 0; r < 4; r++)
        t[ty + r * 8][tx] = W[(size_t)(k0 + ty + r * 8) * DD + n0 + tx];
    __syncthreads();
#pragma unroll
    for (int r = 0; r < 4; r++) {
        int n = n0 + ty + r * 8, k = k0 + tx;
        B2[(size_t)n * DD + k] = __float2half(t[tx][ty + r * 8]);
    }
}

// ---------------------------------------------------------------------------
// mma.sync fp16 GEMM: q and k projections, K=512, fp16 out (unchanged)
// ---------------------------------------------------------------------------
#define MT 128
#define NT 128
#define NKT 8
#define STG 32768u
#define NSTG 3
#define GEMM_SMEM (NSTG * STG)

__device__ __forceinline__ void load_tile(int tile, int stg,
                                          const char* Ab, const char* Bb,
                                          uint32_t sb, int tid) {
    size_t koff = (size_t)tile * 128;
    uint32_t sA = sb + (uint32_t)stg * STG;
    uint32_t sB = sA + 16384u;
#pragma unroll
    for (int c = 0; c < 4; c++) {
        int q = tid + c * 256;
        int r = q >> 3, col = (q & 7) * 16;
        cp16(sA + SWZ128(r * 128 + col), Ab + (size_t)r * 1024 + koff + col);
    }
#pragma unroll
    for (int c = 0; c < 4; c++) {
        int q = tid + c * 256;
        int r = q >> 3, col = (q & 7) * 16;
        cp16(sB + SWZ128(r * 128 + col), Bb + (size_t)r * 1024 + koff + col);
    }
}

__global__ __launch_bounds__(256, 2)
void gemm2() {
    extern __shared__ char smem[];
    uint32_t sb = smem_u32(smem);
    const int tid = threadIdx.x, wid = tid >> 5, lane = tid & 31;
    const int m0 = blockIdx.x * MT;
    const int n0 = blockIdx.y * NT;

    const __half* B2 = blockIdx.z ? g_b2k : g_b2q;
    __half* C       = blockIdx.z ? g_kh : g_qh;

    const char* Ab = (const char*)g_ah + (size_t)m0 * 1024;
    const char* Bb = (const char*)B2 + (size_t)n0 * 1024;

    const int wm = wid & 1;
    const int wn = wid >> 1;

    float acc[4][4][4];
#pragma unroll
    for (int i = 0; i < 4; i++)
#pragma unroll
        for (int j = 0; j < 4; j++)
#pragma unroll
            for (int r = 0; r < 4; r++) acc[i][j][r] = 0.f;

    load_tile(0, 0, Ab, Bb, sb, tid); CP_COMMIT();
    load_tile(1, 1, Ab, Bb, sb, tid); CP_COMMIT();

    const int a_row = wm * 64 + (lane & 15);
    const int a_cg  = (lane >> 4) * 16;
    const int b_row = wn * 32 + (lane & 7);
    const int b_cg  = ((lane >> 3) & 1) * 16;

    for (int t = 0; t < NKT; t++) {
        asm volatile("cp.async.wait_group 1;" ::: "memory");
        __syncthreads();

        if (t + 2 < NKT)
            load_tile(t + 2, (t + 2) % NSTG, Ab, Bb, sb, tid);
        CP_COMMIT();

        uint32_t sA = sb + (uint32_t)(t % NSTG) * STG;
        uint32_t sB = sA + 16384u;
#pragma unroll
        for (int ks = 0; ks < 4; ks++) {
            uint32_t af[4][4], bf[4][2];
#pragma unroll
            for (int mi = 0; mi < 4; mi++)
                ldm_x4(af[mi][0], af[mi][1], af[mi][2], af[mi][3],
                       sA + SWZ128((a_row + mi * 16) * 128 + ks * 32 + a_cg));
#pragma unroll
            for (int ni = 0; ni < 4; ni++)
                ldm_x2(bf[ni][0], bf[ni][1],
                       sB + SWZ128((b_row + ni * 8) * 128 + ks * 32 + b_cg));
#pragma unroll
            for (int mi = 0; mi < 4; mi++)
#pragma unroll
                for (int ni = 0; ni < 4; ni++)
                    mma16816(acc[mi][ni], af[mi], bf[ni]);
        }
    }

    const int er = lane >> 2;
    const int ec = (lane & 3) * 2;
#pragma unroll
    for (int mi = 0; mi < 4; mi++) {
        int r0 = m0 + wm * 64 + mi * 16 + er;
#pragma unroll
        for (int ni = 0; ni < 4; ni++) {
            int cc = n0 + wn * 32 + ni * 8 + ec;
            __half2 v01 = __floats2half2_rn(acc[mi][ni][0], acc[mi][ni][1]);
            __half2 v23 = __floats2half2_rn(acc[mi][ni][2], acc[mi][ni][3]);
            *(__half2*)(C + (size_t)r0 * DD + cc) = v01;
            *(__half2*)(C + (size_t)(r0 + 8) * DD + cc) = v23;
        }
    }
}

// ---------------------------------------------------------------------------
// ctxf v3: fully tensor-core fused block. Per CTA = 16-i block; warp = head.
//  scores S[16x32] = Q_h[16x64] x Kw_h[32x64]^T via MMA (fp32 acc)
//  mask + row softmax on the C fragment (quad shuffles)
//  repack normalized weights in registers as A fragments (C==A layout identity)
//  context out_h[16x512] = W[16x32] x HSw[32x512] via MMA, scatter stores
// smem: q 16KB | kw 32KB | hs 32KB = 80KB -> 2 CTAs/SM. grid (128, 2).
// ---------------------------------------------------------------------------
#define CTXF_SMEM (16384 + 32768 + 32768)   // 81920

__global__ __launch_bounds__(256, 2)
void ctxf(float* __restrict__ out) {
    extern __shared__ char smemraw[];
    uint32_t Qb = smem_u32(smemraw);      // q:  16 rows x 1KB
    uint32_t Kb = Qb + 16384;             // kw: 32 rows x 1KB
    uint32_t Bb = Kb + 32768;             // hs: 32 rows x 1KB

    const int blk = blockIdx.x, b = blockIdx.y;
    const int i0 = blk * 16;
    const int tid = threadIdx.x, wid = tid >> 5, lane = tid & 31;

    // group 0: q rows + kw rows
    {
        const char* qg = (const char*)g_qh + ((size_t)b * SS + i0) * 1024;
        for (int idx = tid; idx < 16 * 64; idx += 256) {
            int r = idx >> 6, u = idx & 63;
            cp16(Qb + r * 1024 + ((u ^ (r & 7)) << 4), qg + (size_t)r * 1024 + u * 16);
        }
        const char* kg = (const char*)g_kh + (size_t)b * SS * 1024;
        for (int idx = tid; idx < 32 * 64; idx += 256) {
            int r = idx >> 6, u = idx & 63;
            int j = i0 - LR + r;
            j = j < 0 ? 0 : (j >= SS ? SS - 1 : j);
            cp16(Kb + r * 1024 + ((u ^ (r & 7)) << 4), kg + (size_t)j * 1024 + u * 16);
        }
        CP_COMMIT();
    }
    // group 1: hs window
    {
        const char* ah = (const char*)g_ah + (size_t)b * SS * 1024;
        for (int idx = tid; idx < 32 * 64; idx += 256) {
            int r = idx >> 6, u = idx & 63;
            int j = i0 - LR + r;
            j = j < 0 ? 0 : (j >= SS ? SS - 1 : j);
            cp16(Bb + r * 1024 + ((u ^ (r & 7)) << 4), ah + (size_t)j * 1024 + u * 16);
        }
        CP_COMMIT();
    }

    asm volatile("cp.async.wait_group 1;" ::: "memory");
    __syncthreads();

    const int h = wid;
    const int er = lane >> 2, ec = (lane & 3) * 2;

    // ---- scores S[16 i][32 jw] via MMA ----
    float s[4][4];
#pragma unroll
    for (int ni = 0; ni < 4; ni++)
#pragma unroll
        for (int r = 0; r < 4; r++) s[ni][r] = 0.f;

#pragma unroll
    for (int ks = 0; ks < 4; ks++) {
        uint32_t af[4];
        {
            int r = lane & 15;
            int u = h * 8 + ks * 2 + (lane >> 4);
            ldm_x4(af[0], af[1], af[2], af[3], Qb + r * 1024 + ((u ^ (r & 7)) << 4));
        }
#pragma unroll
        for (int ni = 0; ni < 4; ni++) {
            uint32_t bf[2];
            int r = ni * 8 + (lane & 7);
            int u = h * 8 + ks * 2 + ((lane >> 3) & 1);
            ldm_x2(bf[0], bf[1], Kb + r * 1024 + ((u ^ (r & 7)) << 4));
            mma16816(s[ni], af, bf);
        }
    }

    // ---- mask + scale ----
#pragma unroll
    for (int ni = 0; ni < 4; ni++)
#pragma unroll
        for (int e = 0; e < 4; e++) {
            int row = (e < 2) ? er : er + 8;
            int col = ni * 8 + ec + (e & 1);
            int j = i0 - LR + col;
            bool valid = (col >= row) && (col <= row + 14) && (j >= 0) && (j < SS);
            s[ni][e] = valid ? s[ni][e] * 0.125f : -1e30f;
        }

    // ---- row softmax (rows er and er+8, each spread over a 4-lane quad) ----
    float m0 = -1e30f, m1 = -1e30f;
#pragma unroll
    for (int ni = 0; ni < 4; ni++) {
        m0 = fmaxf(m0, fmaxf(s[ni][0], s[ni][1]));
        m1 = fmaxf(m1, fmaxf(s[ni][2], s[ni][3]));
    }
    m0 = fmaxf(m0, __shfl_xor_sync(0xffffffffu, m0, 1));
    m0 = fmaxf(m0, __shfl_xor_sync(0xffffffffu, m0, 2));
    m1 = fmaxf(m1, __shfl_xor_sync(0xffffffffu, m1, 1));
    m1 = fmaxf(m1, __shfl_xor_sync(0xffffffffu, m1, 2));

    float s0 = 0.f, s1 = 0.f;
#pragma unroll
    for (int ni = 0; ni < 4; ni++) {
        s[ni][0] = __expf(s[ni][0] - m0); s0 += s[ni][0];
        s[ni][1] = __expf(s[ni][1] - m0); s0 += s[ni][1];
        s[ni][2] = __expf(s[ni][2] - m1); s1 += s[ni][2];
        s[ni][3] = __expf(s[ni][3] - m1); s1 += s[ni][3];
    }
    s0 += __shfl_xor_sync(0xffffffffu, s0, 1);
    s0 += __shfl_xor_sync(0xffffffffu, s0, 2);
    s1 += __shfl_xor_sync(0xffffffffu, s1, 1);
    s1 += __shfl_xor_sync(0xffffffffu, s1, 2);
    float inv0 = 1.f / s0, inv1 = 1.f / s1;

    // ---- repack weights as A fragments (C m16n16 == A m16k16 layout) ----
    uint32_t wa[2][4];
#pragma unroll
    for (int ks = 0; ks < 2; ks++) {
        const int n0t = ks * 2, n1t = ks * 2 + 1;
        wa[ks][0] = packh2(s[n0t][0] * inv0, s[n0t][1] * inv0);
        wa[ks][1] = packh2(s[n0t][2] * inv1, s[n0t][3] * inv1);
        wa[ks][2] = packh2(s[n1t][0] * inv0, s[n1t][1] * inv0);
        wa[ks][3] = packh2(s[n1t][2] * inv1, s[n1t][3] * inv1);
    }

    asm volatile("cp.async.wait_group 0;" ::: "memory");
    __syncthreads();

    // ---- context MMA: out_h[16 x 512] = W[16x32] x HSw[32x512] ----
    float* obase = out + (((size_t)b * HH + h) * SS + i0) * DD;
#pragma unroll
    for (int dp = 0; dp < 8; dp++) {
        float acc[8][4];
#pragma unroll
        for (int ni = 0; ni < 8; ni++)
#pragma unroll
            for (int r = 0; r < 4; r++) acc[ni][r] = 0.f;

#pragma unroll
        for (int ks = 0; ks < 2; ks++) {
#pragma unroll
            for (int ni = 0; ni < 8; ni++) {
                uint32_t bf[2];
                int kr = ks * 16 + (lane & 15);
                int cu = dp * 8 + ni;
                ldm_x2t(bf[0], bf[1], Bb + kr * 1024 + ((cu ^ (kr & 7)) << 4));
                mma16816(acc[ni], wa[ks], bf);
            }
        }

        float* o0 = obase + (size_t)er * DD + dp * 64;
        float* o1 = o0 + 8 * (size_t)DD;
#pragma unroll
        for (int ni = 0; ni < 8; ni++) {
            *(float2*)(o0 + ni * 8 + ec) = make_float2(acc[ni][0], acc[ni][1]);
            *(float2*)(o1 + ni * 8 + ec) = make_float2(acc[ni][2], acc[ni][3]);
        }
    }
}

// ---------------------------------------------------------------------------
extern "C" void kernel_launch(void* const* d_in, const int* in_sizes, int n_in,
                              void* d_out, int out_size) {
    const float* hs = (const float*)d_in[0];
    const float* Wq = (const float*)d_in[1];
    const float* Wk = (const float*)d_in[2];
    float* out = (float*)d_out;

    cudaFuncSetAttribute(gemm2, cudaFuncAttributeMaxDynamicSharedMemorySize, GEMM_SMEM);
    cudaFuncSetAttribute(ctxf, cudaFuncAttributeMaxDynamicSharedMemorySize, CTXF_SMEM);

    split_hs<<<2048, 256>>>(hs);
    split_w<<<dim3(16, 16, 2), dim3(32, 8)>>>(Wq, Wk);
    gemm2<<<dim3(32, 4, 2), 256, GEMM_SMEM>>>();
    ctxf<<<dim3(NBLK, BB), 256, CTXF_SMEM>>>(out);
}